// round 4
// baseline (speedup 1.0000x reference)
#include <cuda_runtime.h>
#include <math.h>

// Problem dims
#define BB 16
#define TT 256
#define SS 256
#define NA 300
#define DD 512
#define HH 8
#define DKK 64
#define DFF 2048
#define LL 6

#define BT (BB*TT)                 // 4096
#define BHTT ((long)BB*HH*TT*TT)   // 8388608

// d_out layout (floats): x | self_attns | enc_attns | ast_attns
#define SELF_OFF 2097152L
#define ENC_OFF  (SELF_OFF + (long)LL*BHTT)
#define AST_OFF  (ENC_OFF  + (long)LL*BHTT)

// ------------- scratch -------------
__device__ float g_x[BT*DD];
__device__ float g_t[BT*DD];
__device__ float g_qkv[3*BT*DD];
__device__ float g_c[BT*DD];
__device__ float g_h[BT*DFF];
__device__ float g_multi[BB*SS*DD];
__device__ float g_ast1[BB*SS*DD];
__device__ float g_aste[BB*SS*DD];
__device__ float g_mm[BB*SS*SS];
__device__ float g_mmctx[BB*SS*DD];

// ------------- tf32 helpers -------------
__device__ __forceinline__ unsigned f2tf(float x) {
    unsigned u; asm("cvt.rna.tf32.f32 %0, %1;" : "=r"(u) : "f"(x)); return u;
}
__device__ __forceinline__ void mma_tf32(float* d,
    unsigned a0, unsigned a1, unsigned a2, unsigned a3,
    unsigned b0, unsigned b1)
{
    asm volatile(
        "mma.sync.aligned.m16n8k8.row.col.f32.tf32.tf32.f32 "
        "{%0,%1,%2,%3},{%4,%5,%6,%7},{%8,%9},{%0,%1,%2,%3};\n"
        : "+f"(d[0]), "+f"(d[1]), "+f"(d[2]), "+f"(d[3])
        : "r"(a0), "r"(a1), "r"(a2), "r"(a3), "r"(b0), "r"(b1));
}

// ---------------------------------------------------------------------
// gemm2: C[M,N] = A[M,K] @ B[K,N], row-major. 64x128x32 tiles, double-
// buffered, fragment-layout smem (LDS.128 / LDS.64 feeds), 256 threads
// (warps 2x4, warp tile 32x32). M%64==0, N%128==0, K%32==0.
// blockIdx.z selects (Az, B + z*strB, C + z*strC).
// A frag region: 16 blocks * 132 words; B frag: 64 blocks * 66 words.
// dynamic smem = 2*(2112 + 4224)*4 = 50688 bytes.
// ---------------------------------------------------------------------
#define ABLK 132
#define BBLK 66
#define BUFW (16*ABLK + 64*BBLK)   // 6336 words per buffer

template<bool RELU, bool ACC>
__global__ __launch_bounds__(256, 2) void gemm2(
    const float* __restrict__ A0, const float* __restrict__ A1,
    const float* __restrict__ A2,
    const float* __restrict__ B0, long strB,
    float* __restrict__ C0, long strC,
    int M, int N, int K)
{
    extern __shared__ unsigned smg[];

    const int tid = threadIdx.x, warp = tid >> 5, lane = tid & 31;
    const int g = lane >> 2, tg = lane & 3;
    const int wr = warp >> 2, wc = warp & 3;     // wr 0..1 (32 rows), wc 0..3 (32 cols)
    const int z = blockIdx.z;

    const float* A = (z == 0) ? A0 : (z == 1 ? A1 : A2);
    const float* At = A + (long)blockIdx.y * 64 * K;
    const float* Bt = B0 + (long)z * strB + blockIdx.x * 128;
    float* C = C0 + (long)z * strC;

    const int aR = tid >> 3, aC = (tid & 7) * 4;   // + p*32 rows
    const int bR = tid >> 5, bC = (tid & 31) * 4;  // + p*8 rows

    float4 ra[2], rb[4];
    #pragma unroll
    for (int p = 0; p < 2; p++)
        ra[p] = *reinterpret_cast<const float4*>(At + (long)(aR + p*32)*K + aC);
    #pragma unroll
    for (int p = 0; p < 4; p++)
        rb[p] = *reinterpret_cast<const float4*>(Bt + (long)(bR + p*8)*N + bC);

    auto sts = [&](int buf) {
        unsigned* Ab = smg + buf*BUFW;
        unsigned* Bb = Ab + 16*ABLK;
        #pragma unroll
        for (int p = 0; p < 2; p++) {
            int m = aR + p*32;
            int mt = m >> 4, gg = m & 7, sm_ = (m >> 3) & 1;
            float vals[4] = {ra[p].x, ra[p].y, ra[p].z, ra[p].w};
            #pragma unroll
            for (int u = 0; u < 4; u++) {
                int k = aC + u;
                int kt = k >> 3, tt = k & 3, sk = (k >> 2) & 1;
                Ab[(mt*4 + kt)*ABLK + (gg*4 + tt)*4 + sm_ + sk*2] = f2tf(vals[u]);
            }
        }
        #pragma unroll
        for (int p = 0; p < 4; p++) {
            int k = bR + p*8;
            int kt = k >> 3, tt = k & 3, sk = (k >> 2) & 1;
            float vals[4] = {rb[p].x, rb[p].y, rb[p].z, rb[p].w};
            #pragma unroll
            for (int u = 0; u < 4; u++) {
                int n = bC + u;
                int nt = n >> 3, gg = n & 7;
                Bb[(nt*4 + kt)*BBLK + (gg*4 + tt)*2 + sk] = f2tf(vals[u]);
            }
        }
    };
    sts(0);
    __syncthreads();

    float acc[8][4];
    #pragma unroll
    for (int i = 0; i < 8; i++) { acc[i][0]=0.f; acc[i][1]=0.f; acc[i][2]=0.f; acc[i][3]=0.f; }

    int cur = 0;
    for (int k0 = 0; k0 < K; k0 += 32) {
        const bool nxt = (k0 + 32) < K;
        if (nxt) {
            #pragma unroll
            for (int p = 0; p < 2; p++)
                ra[p] = *reinterpret_cast<const float4*>(At + (long)(aR + p*32)*K + k0 + 32 + aC);
            #pragma unroll
            for (int p = 0; p < 4; p++)
                rb[p] = *reinterpret_cast<const float4*>(Bt + (long)(k0 + 32 + bR + p*8)*N + bC);
        }
        const unsigned* Ab = smg + cur*BUFW;
        const unsigned* Bb = Ab + 16*ABLK;
        #pragma unroll
        for (int kt = 0; kt < 4; kt++) {
            unsigned a[2][4], b[4][2];
            #pragma unroll
            for (int mi = 0; mi < 2; mi++) {
                uint4 t4 = *reinterpret_cast<const uint4*>(
                    &Ab[((wr*2 + mi)*4 + kt)*ABLK + lane*4]);
                a[mi][0]=t4.x; a[mi][1]=t4.y; a[mi][2]=t4.z; a[mi][3]=t4.w;
            }
            #pragma unroll
            for (int nj = 0; nj < 4; nj++) {
                uint2 t2 = *reinterpret_cast<const uint2*>(
                    &Bb[((wc*4 + nj)*4 + kt)*BBLK + lane*2]);
                b[nj][0]=t2.x; b[nj][1]=t2.y;
            }
            #pragma unroll
            for (int mi = 0; mi < 2; mi++)
                #pragma unroll
                for (int nj = 0; nj < 4; nj++)
                    mma_tf32(acc[mi*4+nj], a[mi][0],a[mi][1],a[mi][2],a[mi][3],
                             b[nj][0], b[nj][1]);
        }
        if (nxt) {
            sts(cur ^ 1);
            __syncthreads();
            cur ^= 1;
        }
    }

    #pragma unroll
    for (int mi = 0; mi < 2; mi++) {
        #pragma unroll
        for (int nj = 0; nj < 4; nj++) {
            float* d = acc[mi*4+nj];
            int r0 = blockIdx.y*64 + wr*32 + mi*16 + g;
            int col = blockIdx.x*128 + wc*32 + nj*8 + tg*2;
            float2 v0 = make_float2(d[0], d[1]);
            float2 v1 = make_float2(d[2], d[3]);
            float2* p0 = reinterpret_cast<float2*>(C + (long)r0*N + col);
            float2* p1 = reinterpret_cast<float2*>(C + (long)(r0+8)*N + col);
            if (ACC) { float2 o0 = *p0, o1 = *p1; v0.x+=o0.x; v0.y+=o0.y; v1.x+=o1.x; v1.y+=o1.y; }
            if (RELU) { v0.x=fmaxf(v0.x,0.f); v0.y=fmaxf(v0.y,0.f); v1.x=fmaxf(v1.x,0.f); v1.y=fmaxf(v1.y,0.f); }
            *p0 = v0; *p1 = v1;
        }
    }
}

// ---------------------------------------------------------------------
// attn_fused: S = scale * Q @ K^T (64 rows x 256 cols), mask, softmax,
// write P to gmem; if CTX, also ctx = P @ V (64 x 64) kept on-chip.
// (unchanged from R3)
// ---------------------------------------------------------------------
template<int MASK, bool CTX>
__global__ __launch_bounds__(256) void attn_fused(
    const float* __restrict__ Q, const float* __restrict__ Km,
    const float* __restrict__ Vm, float* __restrict__ P,
    float* __restrict__ Cctx,
    int Kdim, int lda, int ldb,
    long strA, long offHA, long strB, long offHB,
    int Hh, float scale, const int* __restrict__ tok, int tokStride)
{
    extern __shared__ unsigned sma[];
    unsigned* Qs = sma;                      // 64*68
    unsigned* Ks = sma + 64*68;              // 256*68
    unsigned* Vs = sma + 64*68 + 256*68;     // 256*68 (CTX only)
    unsigned* Ps = sma;                      // 64*260, aliases Qs+Ks head
    __shared__ float red[64*4];

    const int tid = threadIdx.x, warp = tid >> 5, lane = tid & 31;
    const int g = lane >> 2, tg = lane & 3;
    const int wr = warp >> 2, wc = warp & 3;
    const int z = blockIdx.y;
    const int bb = z / Hh, hh = z - bb*Hh;
    const int rowTile = blockIdx.x;
    const int rowBase = rowTile * 64;

    const float* Qb = Q + (long)bb*strA + (long)hh*offHA + (long)rowBase*lda;
    const float* Kb = Km + (long)bb*strB + (long)hh*offHB;

    float acc[16][4];
    #pragma unroll
    for (int i = 0; i < 16; i++) { acc[i][0]=0.f; acc[i][1]=0.f; acc[i][2]=0.f; acc[i][3]=0.f; }

    for (int k0 = 0; k0 < Kdim; k0 += 64) {
        #pragma unroll
        for (int p = 0; p < 4; p++) {            // Q 64x64
            int idx = tid + p*256;
            int r = idx >> 4, c4 = idx & 15;
            float4 v = *reinterpret_cast<const float4*>(Qb + (long)r*lda + k0 + c4*4);
            unsigned* d = &Qs[r*68 + c4*4];
            d[0]=f2tf(v.x); d[1]=f2tf(v.y); d[2]=f2tf(v.z); d[3]=f2tf(v.w);
        }
        #pragma unroll
        for (int p = 0; p < 16; p++) {           // K 256x64
            int idx = tid + p*256;
            int r = idx >> 4, c4 = idx & 15;
            float4 v = *reinterpret_cast<const float4*>(Kb + (long)r*ldb + k0 + c4*4);
            unsigned* d = &Ks[r*68 + c4*4];
            d[0]=f2tf(v.x); d[1]=f2tf(v.y); d[2]=f2tf(v.z); d[3]=f2tf(v.w);
        }
        if (CTX && k0 == 0) {                    // V 256x64 (head slice)
            const float* Vb = Vm + (long)bb*strB + (long)hh*offHB;
            #pragma unroll
            for (int p = 0; p < 16; p++) {
                int idx = tid + p*256;
                int r = idx >> 4, c4 = idx & 15;
                float4 v = *reinterpret_cast<const float4*>(Vb + (long)r*ldb + c4*4);
                unsigned* d = &Vs[r*68 + c4*4];
                d[0]=f2tf(v.x); d[1]=f2tf(v.y); d[2]=f2tf(v.z); d[3]=f2tf(v.w);
            }
        }
        __syncthreads();
        #pragma unroll
        for (int ks = 0; ks < 8; ks++) {
            const int kk = ks * 8;
            unsigned a[2][4], b[8][2];
            #pragma unroll
            for (int mi = 0; mi < 2; mi++) {
                int mb = wr*32 + mi*16;
                a[mi][0] = Qs[(mb+g  )*68 + kk + tg];
                a[mi][1] = Qs[(mb+g+8)*68 + kk + tg];
                a[mi][2] = Qs[(mb+g  )*68 + kk + tg + 4];
                a[mi][3] = Qs[(mb+g+8)*68 + kk + tg + 4];
            }
            #pragma unroll
            for (int nj = 0; nj < 8; nj++) {
                int nb = wc*64 + nj*8;
                b[nj][0] = Ks[(nb+g)*68 + kk + tg];
                b[nj][1] = Ks[(nb+g)*68 + kk + tg + 4];
            }
            #pragma unroll
            for (int mi = 0; mi < 2; mi++)
                #pragma unroll
                for (int nj = 0; nj < 8; nj++)
                    mma_tf32(acc[mi*8+nj], a[mi][0],a[mi][1],a[mi][2],a[mi][3],
                             b[nj][0], b[nj][1]);
        }
        if (k0 + 64 < Kdim) __syncthreads();
    }

    // ---- scale + mask ----
    #pragma unroll
    for (int mi = 0; mi < 2; mi++) {
        #pragma unroll
        for (int nj = 0; nj < 8; nj++) {
            float* d = acc[mi*8+nj];
            int col = wc*64 + nj*8 + tg*2;
            int lr0 = wr*32 + mi*16 + g;
            #pragma unroll
            for (int c = 0; c < 4; c++) {
                int gcol = col + (c & 1);
                int grow = rowBase + lr0 + ((c >> 1) * 8);
                float v = d[c] * scale;
                if (MASK == 1) {
                    if (tok[bb*tokStride + gcol] == 0 || gcol > grow) v = -1e9f;
                } else if (MASK == 2) {
                    if (tok[bb*tokStride + gcol] == 0) v = -1e9f;
                }
                d[c] = v;
            }
        }
    }

    // ---- softmax over full 256-wide rows ----
    float rmax[4];
    #pragma unroll
    for (int mi = 0; mi < 2; mi++) {
        float m0 = -1e30f, m1 = -1e30f;
        #pragma unroll
        for (int nj = 0; nj < 8; nj++) {
            float* d = acc[mi*8+nj];
            m0 = fmaxf(m0, fmaxf(d[0], d[1]));
            m1 = fmaxf(m1, fmaxf(d[2], d[3]));
        }
        rmax[mi*2+0] = m0; rmax[mi*2+1] = m1;
    }
    #pragma unroll
    for (int i = 0; i < 4; i++) {
        rmax[i] = fmaxf(rmax[i], __shfl_xor_sync(0xffffffffu, rmax[i], 1));
        rmax[i] = fmaxf(rmax[i], __shfl_xor_sync(0xffffffffu, rmax[i], 2));
    }
    if (tg == 0) {
        #pragma unroll
        for (int mi = 0; mi < 2; mi++) {
            red[(wr*32 + mi*16 + g    )*4 + wc] = rmax[mi*2+0];
            red[(wr*32 + mi*16 + g + 8)*4 + wc] = rmax[mi*2+1];
        }
    }
    __syncthreads();
    float fmax4[4];
    #pragma unroll
    for (int mi = 0; mi < 2; mi++) {
        int r0 = wr*32 + mi*16 + g, r1 = r0 + 8;
        fmax4[mi*2+0] = fmaxf(fmaxf(red[r0*4+0], red[r0*4+1]), fmaxf(red[r0*4+2], red[r0*4+3]));
        fmax4[mi*2+1] = fmaxf(fmaxf(red[r1*4+0], red[r1*4+1]), fmaxf(red[r1*4+2], red[r1*4+3]));
    }
    __syncthreads();

    float rsum[4] = {0.f, 0.f, 0.f, 0.f};
    #pragma unroll
    for (int mi = 0; mi < 2; mi++) {
        #pragma unroll
        for (int nj = 0; nj < 8; nj++) {
            float* d = acc[mi*8+nj];
            d[0] = __expf(d[0] - fmax4[mi*2+0]);
            d[1] = __expf(d[1] - fmax4[mi*2+0]);
            d[2] = __expf(d[2] - fmax4[mi*2+1]);
            d[3] = __expf(d[3] - fmax4[mi*2+1]);
            rsum[mi*2+0] += d[0] + d[1];
            rsum[mi*2+1] += d[2] + d[3];
        }
    }
    #pragma unroll
    for (int i = 0; i < 4; i++) {
        rsum[i] += __shfl_xor_sync(0xffffffffu, rsum[i], 1);
        rsum[i] += __shfl_xor_sync(0xffffffffu, rsum[i], 2);
    }
    if (tg == 0) {
        #pragma unroll
        for (int mi = 0; mi < 2; mi++) {
            red[(wr*32 + mi*16 + g    )*4 + wc] = rsum[mi*2+0];
            red[(wr*32 + mi*16 + g + 8)*4 + wc] = rsum[mi*2+1];
        }
    }
    __syncthreads();
    float rinv[4];
    #pragma unroll
    for (int mi = 0; mi < 2; mi++) {
        int r0 = wr*32 + mi*16 + g, r1 = r0 + 8;
        rinv[mi*2+0] = 1.f / (red[r0*4+0] + red[r0*4+1] + red[r0*4+2] + red[r0*4+3]);
        rinv[mi*2+1] = 1.f / (red[r1*4+0] + red[r1*4+1] + red[r1*4+2] + red[r1*4+3]);
    }

    // ---- write P to gmem (+ Ps smem for ctx) ----
    float* Pb = P + (long)z * 65536L + (long)rowBase * 256;
    #pragma unroll
    for (int mi = 0; mi < 2; mi++) {
        #pragma unroll
        for (int nj = 0; nj < 8; nj++) {
            float* d = acc[mi*8+nj];
            int col = wc*64 + nj*8 + tg*2;
            int r0 = wr*32 + mi*16 + g;
            float p0 = d[0]*rinv[mi*2+0], p1 = d[1]*rinv[mi*2+0];
            float p2 = d[2]*rinv[mi*2+1], p3 = d[3]*rinv[mi*2+1];
            *reinterpret_cast<float2*>(Pb + (long)r0*256 + col) = make_float2(p0, p1);
            *reinterpret_cast<float2*>(Pb + (long)(r0+8)*256 + col) = make_float2(p2, p3);
            if (CTX) {
                Ps[r0*260 + col] = f2tf(p0); Ps[r0*260 + col + 1] = f2tf(p1);
                Ps[(r0+8)*260 + col] = f2tf(p2); Ps[(r0+8)*260 + col + 1] = f2tf(p3);
            }
        }
    }

    if (CTX) {
        __syncthreads();
        float acc2[4][4];
        #pragma unroll
        for (int i = 0; i < 4; i++) { acc2[i][0]=0.f; acc2[i][1]=0.f; acc2[i][2]=0.f; acc2[i][3]=0.f; }
        #pragma unroll 8
        for (int ks = 0; ks < 32; ks++) {
            const int kk = ks * 8;
            unsigned a[2][4], b[2][2];
            #pragma unroll
            for (int mi = 0; mi < 2; mi++) {
                int mb = wr*32 + mi*16;
                a[mi][0] = Ps[(mb+g  )*260 + kk + tg];
                a[mi][1] = Ps[(mb+g+8)*260 + kk + tg];
                a[mi][2] = Ps[(mb+g  )*260 + kk + tg + 4];
                a[mi][3] = Ps[(mb+g+8)*260 + kk + tg + 4];
            }
            #pragma unroll
            for (int nj = 0; nj < 2; nj++) {
                int nb = wc*16 + nj*8;
                b[nj][0] = Vs[(kk+tg  )*68 + nb + g];
                b[nj][1] = Vs[(kk+tg+4)*68 + nb + g];
            }
            #pragma unroll
            for (int mi = 0; mi < 2; mi++)
                #pragma unroll
                for (int nj = 0; nj < 2; nj++)
                    mma_tf32(acc2[mi*2+nj], a[mi][0],a[mi][1],a[mi][2],a[mi][3],
                             b[nj][0], b[nj][1]);
        }
        float* Cb = Cctx + (long)bb*TT*DD + hh*64;
        #pragma unroll
        for (int mi = 0; mi < 2; mi++) {
            #pragma unroll
            for (int nj = 0; nj < 2; nj++) {
                float* d = acc2[mi*2+nj];
                int r0 = rowBase + wr*32 + mi*16 + g;
                int col = wc*16 + nj*8 + tg*2;
                *reinterpret_cast<float2*>(Cb + (long)r0*DD + col) = make_float2(d[0], d[1]);
                *reinterpret_cast<float2*>(Cb + (long)(r0+8)*DD + col) = make_float2(d[2], d[3]);
            }
        }
    }
}

// ---------------------------------------------------------------------
// bgemm_tf32 (preamble: conv1d K=300, mm_ctx) — unchanged.
// ---------------------------------------------------------------------
template<bool ROWBIAS>
__global__ __launch_bounds__(256) void bgemm_tf32(
    const float* __restrict__ A, const float* __restrict__ B,
    float* __restrict__ C, int M, int N, int K,
    int lda, int ldb, int ldc,
    long strA, long offHA, long strB, long offHB, long strC, long offHC,
    int Hh, const float* __restrict__ bias)
{
    __shared__ unsigned As[128*36];
    __shared__ unsigned Bs[32*72];
    const int tid = threadIdx.x, warp = tid >> 5, lane = tid & 31;
    const int g = lane >> 2, tg = lane & 3;
    const int wr = warp >> 1, wc = warp & 1;
    const int z = blockIdx.z;
    const int bb = z / Hh, hh = z - bb*Hh;

    const float* Ab = A + (long)bb*strA + (long)hh*offHA + (long)blockIdx.y*128*lda;
    const float* Bb = B + (long)bb*strB + (long)hh*offHB + (long)blockIdx.x*64;

    float acc[8][4];
    #pragma unroll
    for (int i = 0; i < 8; i++) { acc[i][0]=0.f; acc[i][1]=0.f; acc[i][2]=0.f; acc[i][3]=0.f; }

    for (int k0 = 0; k0 < K; k0 += 32) {
        if (k0 + 32 <= K && (lda & 3) == 0) {
            #pragma unroll
            for (int p = 0; p < 4; p++) {
                int idx = tid + p*256;
                int r = idx >> 3, c4 = idx & 7;
                float4 v = *reinterpret_cast<const float4*>(Ab + (long)r*lda + k0 + c4*4);
                unsigned* d = &As[r*36 + c4*4];
                d[0]=f2tf(v.x); d[1]=f2tf(v.y); d[2]=f2tf(v.z); d[3]=f2tf(v.w);
            }
        } else {
            #pragma unroll
            for (int p = 0; p < 16; p++) {
                int idx = tid + p*256;
                int r = idx >> 5, c = idx & 31;
                float v = (k0 + c < K) ? Ab[(long)r*lda + k0 + c] : 0.f;
                As[r*36 + c] = f2tf(v);
            }
        }
        #pragma unroll
        for (int p = 0; p < 2; p++) {
            int idx = tid + p*256;
            int r = idx >> 4, c4 = idx & 15;
            float4 v;
            if (k0 + r < K)
                v = *reinterpret_cast<const float4*>(Bb + (long)(k0 + r)*ldb + c4*4);
            else
                v = make_float4(0.f, 0.f, 0.f, 0.f);
            unsigned* d = &Bs[r*72 + c4*4];
            d[0]=f2tf(v.x); d[1]=f2tf(v.y); d[2]=f2tf(v.z); d[3]=f2tf(v.w);
        }
        __syncthreads();
        #pragma unroll
        for (int ks = 0; ks < 4; ks++) {
            const int kk = ks * 8;
            unsigned a[2][4], b[4][2];
            #pragma unroll
            for (int mi = 0; mi < 2; mi++) {
                int mb = wr*32 + mi*16;
                a[mi][0] = As[(mb+g  )*36 + kk + tg];
                a[mi][1] = As[(mb+g+8)*36 + kk + tg];
                a[mi][2] = As[(mb+g  )*36 + kk + tg + 4];
                a[mi][3] = As[(mb+g+8)*36 + kk + tg + 4];
            }
            #pragma unroll
            for (int nj = 0; nj < 4; nj++) {
                int nb = wc*32 + nj*8;
                b[nj][0] = Bs[(kk+tg  )*72 + nb + g];
                b[nj][1] = Bs[(kk+tg+4)*72 + nb + g];
            }
            #pragma unroll
            for (int mi = 0; mi < 2; mi++)
                #pragma unroll
                for (int nj = 0; nj < 4; nj++)
                    mma_tf32(acc[mi*4+nj], a[mi][0],a[mi][1],a[mi][2],a[mi][3],
                             b[nj][0], b[nj][1]);
        }
        __syncthreads();
    }

    float* Cb = C + (long)bb*strC + (long)hh*offHC;
    #pragma unroll
    for (int mi = 0; mi < 2; mi++) {
        #pragma unroll
        for (int nj = 0; nj < 4; nj++) {
            float* d = acc[mi*4+nj];
            int r0 = blockIdx.y*128 + wr*32 + mi*16 + g;
            int col = blockIdx.x*64 + wc*32 + nj*8 + tg*2;
            float b0 = ROWBIAS ? bias[r0] : 0.f;
            float b1 = ROWBIAS ? bias[r0+8] : 0.f;
            *reinterpret_cast<float2*>(Cb + (long)r0*ldc + col) =
                make_float2(d[0]+b0, d[1]+b0);
            *reinterpret_cast<float2*>(Cb + (long)(r0+8)*ldc + col) =
                make_float2(d[2]+b1, d[3]+b1);
        }
    }
}

// ---------------------------------------------------------------------
__global__ __launch_bounds__(256) void add_ln(
    const float* __restrict__ a, const float* __restrict__ b,
    float* __restrict__ out, const float* __restrict__ g,
    const float* __restrict__ beta)
{
    long off = (long)blockIdx.x * DD;
    int t = threadIdx.x;
    float v0 = a[off + t] + b[off + t];
    float v1 = a[off + t + 256] + b[off + t + 256];
    __shared__ float red[256];
    red[t] = v0 + v1; __syncthreads();
    for (int s = 128; s > 0; s >>= 1) { if (t < s) red[t] += red[t+s]; __syncthreads(); }
    float mu = red[0] * (1.f/DD); __syncthreads();
    float d0 = v0 - mu, d1 = v1 - mu;
    red[t] = d0*d0 + d1*d1; __syncthreads();
    for (int s = 128; s > 0; s >>= 1) { if (t < s) red[t] += red[t+s]; __syncthreads(); }
    float rstd = rsqrtf(red[0] * (1.f/DD) + 1e-5f);
    float g0 = g ? g[t] : 1.f,       g1 = g ? g[t+256] : 1.f;
    float b0 = beta ? beta[t] : 0.f, b1 = beta ? beta[t+256] : 0.f;
    out[off + t]       = d0 * rstd * g0 + b0;
    out[off + t + 256] = d1 * rstd * g1 + b1;
}

__global__ void embed_pe(const int* __restrict__ dec,
                         const float* __restrict__ emb,
                         float* __restrict__ x)
{
    long idx = (long)blockIdx.x * blockDim.x + threadIdx.x;
    if (idx >= (long)BT*DD) return;
    int d  = (int)(idx % DD);
    long bt = idx / DD;
    int t  = (int)(bt % TT);
    int tokidx = dec[bt];
    int d2 = d & ~1;
    float div = expf(-logf(10000.f) * (float)d2 / (float)DD);
    float ang = (float)t * div;
    float pe = (d & 1) ? cosf(ang) : sinf(ang);
    x[idx] = emb[(long)tokidx*DD + d] + pe;
}

__global__ void add3(const float* __restrict__ a, const float* __restrict__ bias,
                     const float* __restrict__ c, float* __restrict__ out, long n)
{
    long i = (long)blockIdx.x * blockDim.x + threadIdx.x;
    if (i >= n) return;
    out[i] = a[i] + bias[i % DD] + c[i];
}

__global__ void copyk(const float* __restrict__ src, float* __restrict__ dst, long n)
{
    long i = (long)blockIdx.x * blockDim.x + threadIdx.x;
    if (i < n) dst[i] = src[i];
}

// ---------------------------------------------------------------------
extern "C" void kernel_launch(void* const* d_in, const int* in_sizes, int n_in,
                              void* d_out, int out_size)
{
    const int*   dec     = (const int*)  d_in[0];
    const int*   enc     = (const int*)  d_in[1];
    const float* enc_out = (const float*)d_in[2];
    const float* ast_out = (const float*)d_in[3];
    const float* src_emb = (const float*)d_in[4];
    const float* ast_emb = (const float*)d_in[5];
    const float* emb     = (const float*)d_in[7];
    const float* attn_W  = (const float*)d_in[8];
    const float* ln_g    = (const float*)d_in[9];
    const float* ln_b    = (const float*)d_in[10];
    const float* W1      = (const float*)d_in[11];
    const float* W2      = (const float*)d_in[12];
    const float* conv_w  = (const float*)d_in[13];
    const float* conv_b  = (const float*)d_in[14];
    const float* mffnW   = (const float*)d_in[15];
    const float* mffnb   = (const float*)d_in[16];
    float* out = (float*)d_out;

    float *x,*t,*qkv,*c,*h,*multi,*ast1,*aste,*mm,*mmctx;
    cudaGetSymbolAddress((void**)&x,     g_x);
    cudaGetSymbolAddress((void**)&t,     g_t);
    cudaGetSymbolAddress((void**)&qkv,   g_qkv);
    cudaGetSymbolAddress((void**)&c,     g_c);
    cudaGetSymbolAddress((void**)&h,     g_h);
    cudaGetSymbolAddress((void**)&multi, g_multi);
    cudaGetSymbolAddress((void**)&ast1,  g_ast1);
    cudaGetSymbolAddress((void**)&aste,  g_aste);
    cudaGetSymbolAddress((void**)&mm,    g_mm);
    cudaGetSymbolAddress((void**)&mmctx, g_mmctx);

    const int GM_SMEM  = 2*BUFW*4;                             // 50688
    const int AT_SMEM  = (64*68 + 2*256*68)*4;                 // 156672 (CTX)
    const int MM_SMEM  = (64*68 + 256*68)*4;                   // 87040  (no CTX)
    cudaFuncSetAttribute(gemm2<false,false>, cudaFuncAttributeMaxDynamicSharedMemorySize, GM_SMEM);
    cudaFuncSetAttribute(gemm2<false,true >, cudaFuncAttributeMaxDynamicSharedMemorySize, GM_SMEM);
    cudaFuncSetAttribute(gemm2<true ,false>, cudaFuncAttributeMaxDynamicSharedMemorySize, GM_SMEM);
    cudaFuncSetAttribute(attn_fused<0,false>, cudaFuncAttributeMaxDynamicSharedMemorySize, MM_SMEM);
    cudaFuncSetAttribute(attn_fused<0,true >, cudaFuncAttributeMaxDynamicSharedMemorySize, AT_SMEM);
    cudaFuncSetAttribute(attn_fused<1,true >, cudaFuncAttributeMaxDynamicSharedMemorySize, AT_SMEM);
    cudaFuncSetAttribute(attn_fused<2,true >, cudaFuncAttributeMaxDynamicSharedMemorySize, AT_SMEM);

    float* q = qkv;
    float* k = qkv + (long)BT*DD;
    float* v = qkv + 2L*BT*DD;

    // ---------------- multi_model preamble ----------------
    {
        dim3 grid(DD/64, SS/128, BB);
        bgemm_tf32<true><<<grid, 256>>>(conv_w, ast_out, ast1,
            SS, DD, NA, NA, DD, DD,
            0L, 0L, (long)NA*DD, 0L, (long)SS*DD, 0L, 1, conv_b);
        bgemm_tf32<true><<<grid, 256>>>(conv_w, ast_emb, aste,
            SS, DD, NA, NA, DD, DD,
            0L, 0L, (long)NA*DD, 0L, (long)SS*DD, 0L, 1, conv_b);
    }
    {
        dim3 gs(SS/64, BB);
        attn_fused<0,false><<<gs, 256, MM_SMEM>>>(ast1, enc_out, nullptr, mm, nullptr,
            DD, DD, DD, (long)SS*DD, 0L, (long)SS*DD, 0L,
            1, 0.125f, nullptr, 0);
        dim3 grid2(DD/64, SS/128, BB);
        bgemm_tf32<false><<<grid2, 256>>>(mm, enc_out, mmctx,
            SS, DD, SS, SS, DD, DD,
            (long)SS*SS, 0L, (long)SS*DD, 0L, (long)SS*DD, 0L, 1, nullptr);
    }
    {
        dim3 grid(DD/128, BT/64, 1);
        gemm2<false,false><<<grid, 256, GM_SMEM>>>(src_emb, src_emb, src_emb,
            mffnW, 0L, t, 0L, BT, DD, DD);
        gemm2<false,true ><<<grid, 256, GM_SMEM>>>(aste, aste, aste,
            mffnW + DD*DD, 0L, t, 0L, BT, DD, DD);
        long n = (long)BB*SS*DD;
        add3<<<(int)((n + 255)/256), 256>>>(t, mffnb, mmctx, multi, n);
    }
    embed_pe<<<(BT*DD + 255)/256, 256>>>(dec, emb, x);

    // ---------------- decoder layers ----------------
    dim3 gQKV(DD/128, BT/64, 3);
    dim3 gProj(DD/128, BT/64, 1);
    dim3 gF1(DFF/128, BT/64, 1);
    dim3 gScore(TT/64, BB*HH);

    for (int l = 0; l < LL; l++) {
        for (int a = 0; a < 3; a++) {
            const float* W = attn_W + ((long)(l*3 + a) * 4) * DD * DD;
            const float* Wo = W + 3L*DD*DD;
            const float* xk = (a == 0) ? x : (a == 1 ? enc_out : multi);

            gemm2<false,false><<<gQKV, 256, GM_SMEM>>>(x, xk, xk,
                W, (long)DD*DD, qkv, (long)BT*DD, BT, DD, DD);

            long attnBase = (a == 0 ? SELF_OFF : (a == 1 ? ENC_OFF : AST_OFF))
                            + (long)l * BHTT;
            float* P = out + attnBase;

            if (a == 0)
                attn_fused<1,true><<<gScore, 256, AT_SMEM>>>(q, k, v, P, c,
                    DKK, DD, DD, (long)TT*DD, 64L, (long)TT*DD, 64L,
                    HH, 0.125f, dec, TT);
            else if (a == 1)
                attn_fused<2,true><<<gScore, 256, AT_SMEM>>>(q, k, v, P, c,
                    DKK, DD, DD, (long)TT*DD, 64L, (long)TT*DD, 64L,
                    HH, 0.125f, enc, SS);
            else
                attn_fused<0,true><<<gScore, 256, AT_SMEM>>>(q, k, v, P, c,
                    DKK, DD, DD, (long)TT*DD, 64L, (long)TT*DD, 64L,
                    HH, 0.125f, nullptr, 0);

            gemm2<false,false><<<gProj, 256, GM_SMEM>>>(c, c, c,
                Wo, 0L, t, 0L, BT, DD, DD);
            add_ln<<<BT, 256>>>(t, x, x,
                ln_g + (long)(l*3 + a)*DD, ln_b + (long)(l*3 + a)*DD);
        }
        gemm2<true ,false><<<gF1, 256, GM_SMEM>>>(x, x, x,
            W1 + (long)l*DD*DFF, 0L, h, 0L, BT, DFF, DD);
        gemm2<false,false><<<gProj, 256, GM_SMEM>>>(h, h, h,
            W2 + (long)l*DFF*DD, 0L, t, 0L, BT, DD, DFF);
        add_ln<<<BT, 256>>>(t, x, x, nullptr, nullptr);
    }

    copyk<<<(BT*DD + 255)/256, 256>>>(x, out, (long)BT*DD);
}

// round 5
// speedup vs baseline: 1.8294x; 1.8294x over previous
#include <cuda_runtime.h>
#include <cuda_fp16.h>
#include <math.h>

// Problem dims
#define BB 16
#define TT 256
#define SS 256
#define NA 300
#define DD 512
#define HH 8
#define DKK 64
#define DFF 2048
#define LL 6

#define BT (BB*TT)                 // 4096
#define BHTT ((long)BB*HH*TT*TT)   // 8388608

// d_out layout (floats): x | self_attns | enc_attns | ast_attns
#define SELF_OFF 2097152L
#define ENC_OFF  (SELF_OFF + (long)LL*BHTT)
#define AST_OFF  (ENC_OFF  + (long)LL*BHTT)

// ------------- scratch -------------
__device__ float g_x[BT*DD];
__device__ float g_t[BT*DD];
__device__ float g_qkv[3*BT*DD];
__device__ float g_c[BT*DD];
__device__ float g_h[BT*DFF];
__device__ float g_multi[BB*SS*DD];
__device__ float g_ast1[BB*SS*DD];
__device__ float g_aste[BB*SS*DD];
__device__ float g_mm[BB*SS*SS];
__device__ float g_mmctx[BB*SS*DD];

// ------------- helpers -------------
__device__ __forceinline__ unsigned f2tf(float x) {
    unsigned u; asm("cvt.rna.tf32.f32 %0, %1;" : "=r"(u) : "f"(x)); return u;
}
__device__ __forceinline__ void mma_tf32(float* d,
    unsigned a0, unsigned a1, unsigned a2, unsigned a3,
    unsigned b0, unsigned b1)
{
    asm volatile(
        "mma.sync.aligned.m16n8k8.row.col.f32.tf32.tf32.f32 "
        "{%0,%1,%2,%3},{%4,%5,%6,%7},{%8,%9},{%0,%1,%2,%3};\n"
        : "+f"(d[0]), "+f"(d[1]), "+f"(d[2]), "+f"(d[3])
        : "r"(a0), "r"(a1), "r"(a2), "r"(a3), "r"(b0), "r"(b1));
}
__device__ __forceinline__ unsigned pack_h2(float x, float y) {
    __half2 h = __floats2half2_rn(x, y);
    return *reinterpret_cast<unsigned*>(&h);
}
__device__ __forceinline__ void mma_f16(float* d,
    unsigned a0, unsigned a1, unsigned a2, unsigned a3,
    unsigned b0, unsigned b1)
{
    asm volatile(
        "mma.sync.aligned.m16n8k16.row.col.f32.f16.f16.f32 "
        "{%0,%1,%2,%3},{%4,%5,%6,%7},{%8,%9},{%0,%1,%2,%3};\n"
        : "+f"(d[0]), "+f"(d[1]), "+f"(d[2]), "+f"(d[3])
        : "r"(a0), "r"(a1), "r"(a2), "r"(a3), "r"(b0), "r"(b1));
}

// ---------------------------------------------------------------------
// gemm2 (fp16 MMA, fp32 accum): C[M,N] = A[M,K] @ B[K,N], row-major.
// 64x128x32 tiles, double-buffered, 256 threads (warps 2x4, warp 32x32).
// M%64==0, N%128==0, K%32==0. blockIdx.z selects (Az, B+z*strB, C+z*strC).
// smem: A as half2 V[m][k2] (64 x 16, row pad 20); B as half2 W[k2][n]
// (16 x 128, row pad 136). dyn smem = 2*(64*20 + 16*136)*4 = 27648 B.
// ---------------------------------------------------------------------
#define VP 20
#define WP 136
#define BUFW (64*VP + 16*WP)   // 3456 words

template<bool RELU, bool ACC>
__global__ __launch_bounds__(256, 2) void gemm2(
    const float* __restrict__ A0, const float* __restrict__ A1,
    const float* __restrict__ A2,
    const float* __restrict__ B0, long strB,
    float* __restrict__ C0, long strC,
    int M, int N, int K)
{
    extern __shared__ unsigned smg[];

    const int tid = threadIdx.x, warp = tid >> 5, lane = tid & 31;
    const int g = lane >> 2, tg = lane & 3;
    const int wr = warp >> 2, wc = warp & 3;     // wr 0..1 (32 rows), wc 0..3 (32 cols)
    const int z = blockIdx.z;

    const float* A = (z == 0) ? A0 : (z == 1 ? A1 : A2);
    const float* At = A + (long)blockIdx.y * 64 * K;
    const float* Bt = B0 + (long)z * strB + blockIdx.x * 128;
    float* C = C0 + (long)z * strC;

    const int aR = tid >> 3;          // 0..31 (+32)
    const int aC = (tid & 7) * 4;     // k offset within slab
    const int kp = tid >> 5;          // 0..7: B k-pair
    const int bC = (tid & 31) * 4;    // n offset

    float4 ra[2], rb[4];
    #pragma unroll
    for (int p = 0; p < 2; p++)
        ra[p] = *reinterpret_cast<const float4*>(At + (long)(aR + p*32)*K + aC);
    rb[0] = *reinterpret_cast<const float4*>(Bt + (long)(2*kp     )*N + bC);
    rb[1] = *reinterpret_cast<const float4*>(Bt + (long)(2*kp + 1 )*N + bC);
    rb[2] = *reinterpret_cast<const float4*>(Bt + (long)(2*kp + 16)*N + bC);
    rb[3] = *reinterpret_cast<const float4*>(Bt + (long)(2*kp + 17)*N + bC);

    auto sts = [&](int buf) {
        unsigned* V = smg + buf*BUFW;
        unsigned* W = V + 64*VP;
        #pragma unroll
        for (int p = 0; p < 2; p++) {
            int m = aR + p*32;
            uint2 w;
            w.x = pack_h2(ra[p].x, ra[p].y);
            w.y = pack_h2(ra[p].z, ra[p].w);
            *reinterpret_cast<uint2*>(&V[m*VP + (aC >> 1)]) = w;
        }
        {
            uint4 w0, w1;
            w0.x = pack_h2(rb[0].x, rb[1].x); w0.y = pack_h2(rb[0].y, rb[1].y);
            w0.z = pack_h2(rb[0].z, rb[1].z); w0.w = pack_h2(rb[0].w, rb[1].w);
            *reinterpret_cast<uint4*>(&W[kp*WP + bC]) = w0;
            w1.x = pack_h2(rb[2].x, rb[3].x); w1.y = pack_h2(rb[2].y, rb[3].y);
            w1.z = pack_h2(rb[2].z, rb[3].z); w1.w = pack_h2(rb[2].w, rb[3].w);
            *reinterpret_cast<uint4*>(&W[(kp+8)*WP + bC]) = w1;
        }
    };
    sts(0);
    __syncthreads();

    float acc[8][4];
    #pragma unroll
    for (int i = 0; i < 8; i++) { acc[i][0]=0.f; acc[i][1]=0.f; acc[i][2]=0.f; acc[i][3]=0.f; }

    int cur = 0;
    for (int k0 = 0; k0 < K; k0 += 32) {
        const bool nxt = (k0 + 32) < K;
        if (nxt) {
            #pragma unroll
            for (int p = 0; p < 2; p++)
                ra[p] = *reinterpret_cast<const float4*>(At + (long)(aR + p*32)*K + k0 + 32 + aC);
            rb[0] = *reinterpret_cast<const float4*>(Bt + (long)(k0 + 32 + 2*kp     )*N + bC);
            rb[1] = *reinterpret_cast<const float4*>(Bt + (long)(k0 + 32 + 2*kp + 1 )*N + bC);
            rb[2] = *reinterpret_cast<const float4*>(Bt + (long)(k0 + 32 + 2*kp + 16)*N + bC);
            rb[3] = *reinterpret_cast<const float4*>(Bt + (long)(k0 + 32 + 2*kp + 17)*N + bC);
        }
        const unsigned* V = smg + cur*BUFW;
        const unsigned* W = V + 64*VP;
        #pragma unroll
        for (int kt = 0; kt < 2; kt++) {
            unsigned a[2][4], b[4][2];
            #pragma unroll
            for (int mi = 0; mi < 2; mi++) {
                int r0 = (wr*32 + mi*16 + g)*VP + kt*8 + tg;
                a[mi][0] = V[r0];
                a[mi][1] = V[r0 + 8*VP];
                a[mi][2] = V[r0 + 4];
                a[mi][3] = V[r0 + 8*VP + 4];
            }
            #pragma unroll
            for (int nj = 0; nj < 4; nj++) {
                int nb = wc*32 + nj*8 + g;
                b[nj][0] = W[(kt*8 + tg    )*WP + nb];
                b[nj][1] = W[(kt*8 + tg + 4)*WP + nb];
            }
            #pragma unroll
            for (int mi = 0; mi < 2; mi++)
                #pragma unroll
                for (int nj = 0; nj < 4; nj++)
                    mma_f16(acc[mi*4+nj], a[mi][0],a[mi][1],a[mi][2],a[mi][3],
                            b[nj][0], b[nj][1]);
        }
        if (nxt) {
            sts(cur ^ 1);
            __syncthreads();
            cur ^= 1;
        }
    }

    #pragma unroll
    for (int mi = 0; mi < 2; mi++) {
        #pragma unroll
        for (int nj = 0; nj < 4; nj++) {
            float* d = acc[mi*4+nj];
            int r0 = blockIdx.y*64 + wr*32 + mi*16 + g;
            int col = blockIdx.x*128 + wc*32 + nj*8 + tg*2;
            float2 v0 = make_float2(d[0], d[1]);
            float2 v1 = make_float2(d[2], d[3]);
            float2* p0 = reinterpret_cast<float2*>(C + (long)r0*N + col);
            float2* p1 = reinterpret_cast<float2*>(C + (long)(r0+8)*N + col);
            if (ACC) { float2 o0 = *p0, o1 = *p1; v0.x+=o0.x; v0.y+=o0.y; v1.x+=o1.x; v1.y+=o1.y; }
            if (RELU) { v0.x=fmaxf(v0.x,0.f); v0.y=fmaxf(v0.y,0.f); v1.x=fmaxf(v1.x,0.f); v1.y=fmaxf(v1.y,0.f); }
            *p0 = v0; *p1 = v1;
        }
    }
}

// ---------------------------------------------------------------------
// attn_fused (tf32, unchanged from R3)
// ---------------------------------------------------------------------
template<int MASK, bool CTX>
__global__ __launch_bounds__(256) void attn_fused(
    const float* __restrict__ Q, const float* __restrict__ Km,
    const float* __restrict__ Vm, float* __restrict__ P,
    float* __restrict__ Cctx,
    int Kdim, int lda, int ldb,
    long strA, long offHA, long strB, long offHB,
    int Hh, float scale, const int* __restrict__ tok, int tokStride)
{
    extern __shared__ unsigned sma[];
    unsigned* Qs = sma;                      // 64*68
    unsigned* Ks = sma + 64*68;              // 256*68
    unsigned* Vs = sma + 64*68 + 256*68;     // 256*68 (CTX only)
    unsigned* Ps = sma;                      // 64*260, aliases Qs+Ks head
    __shared__ float red[64*4];

    const int tid = threadIdx.x, warp = tid >> 5, lane = tid & 31;
    const int g = lane >> 2, tg = lane & 3;
    const int wr = warp >> 2, wc = warp & 3;
    const int z = blockIdx.y;
    const int bb = z / Hh, hh = z - bb*Hh;
    const int rowTile = blockIdx.x;
    const int rowBase = rowTile * 64;

    const float* Qb = Q + (long)bb*strA + (long)hh*offHA + (long)rowBase*lda;
    const float* Kb = Km + (long)bb*strB + (long)hh*offHB;

    float acc[16][4];
    #pragma unroll
    for (int i = 0; i < 16; i++) { acc[i][0]=0.f; acc[i][1]=0.f; acc[i][2]=0.f; acc[i][3]=0.f; }

    for (int k0 = 0; k0 < Kdim; k0 += 64) {
        #pragma unroll
        for (int p = 0; p < 4; p++) {            // Q 64x64
            int idx = tid + p*256;
            int r = idx >> 4, c4 = idx & 15;
            float4 v = *reinterpret_cast<const float4*>(Qb + (long)r*lda + k0 + c4*4);
            unsigned* d = &Qs[r*68 + c4*4];
            d[0]=f2tf(v.x); d[1]=f2tf(v.y); d[2]=f2tf(v.z); d[3]=f2tf(v.w);
        }
        #pragma unroll
        for (int p = 0; p < 16; p++) {           // K 256x64
            int idx = tid + p*256;
            int r = idx >> 4, c4 = idx & 15;
            float4 v = *reinterpret_cast<const float4*>(Kb + (long)r*ldb + k0 + c4*4);
            unsigned* d = &Ks[r*68 + c4*4];
            d[0]=f2tf(v.x); d[1]=f2tf(v.y); d[2]=f2tf(v.z); d[3]=f2tf(v.w);
        }
        if (CTX && k0 == 0) {                    // V 256x64 (head slice)
            const float* Vb = Vm + (long)bb*strB + (long)hh*offHB;
            #pragma unroll
            for (int p = 0; p < 16; p++) {
                int idx = tid + p*256;
                int r = idx >> 4, c4 = idx & 15;
                float4 v = *reinterpret_cast<const float4*>(Vb + (long)r*ldb + c4*4);
                unsigned* d = &Vs[r*68 + c4*4];
                d[0]=f2tf(v.x); d[1]=f2tf(v.y); d[2]=f2tf(v.z); d[3]=f2tf(v.w);
            }
        }
        __syncthreads();
        #pragma unroll
        for (int ks = 0; ks < 8; ks++) {
            const int kk = ks * 8;
            unsigned a[2][4], b[8][2];
            #pragma unroll
            for (int mi = 0; mi < 2; mi++) {
                int mb = wr*32 + mi*16;
                a[mi][0] = Qs[(mb+g  )*68 + kk + tg];
                a[mi][1] = Qs[(mb+g+8)*68 + kk + tg];
                a[mi][2] = Qs[(mb+g  )*68 + kk + tg + 4];
                a[mi][3] = Qs[(mb+g+8)*68 + kk + tg + 4];
            }
            #pragma unroll
            for (int nj = 0; nj < 8; nj++) {
                int nb = wc*64 + nj*8;
                b[nj][0] = Ks[(nb+g)*68 + kk + tg];
                b[nj][1] = Ks[(nb+g)*68 + kk + tg + 4];
            }
            #pragma unroll
            for (int mi = 0; mi < 2; mi++)
                #pragma unroll
                for (int nj = 0; nj < 8; nj++)
                    mma_tf32(acc[mi*8+nj], a[mi][0],a[mi][1],a[mi][2],a[mi][3],
                             b[nj][0], b[nj][1]);
        }
        if (k0 + 64 < Kdim) __syncthreads();
    }

    // ---- scale + mask ----
    #pragma unroll
    for (int mi = 0; mi < 2; mi++) {
        #pragma unroll
        for (int nj = 0; nj < 8; nj++) {
            float* d = acc[mi*8+nj];
            int col = wc*64 + nj*8 + tg*2;
            int lr0 = wr*32 + mi*16 + g;
            #pragma unroll
            for (int c = 0; c < 4; c++) {
                int gcol = col + (c & 1);
                int grow = rowBase + lr0 + ((c >> 1) * 8);
                float v = d[c] * scale;
                if (MASK == 1) {
                    if (tok[bb*tokStride + gcol] == 0 || gcol > grow) v = -1e9f;
                } else if (MASK == 2) {
                    if (tok[bb*tokStride + gcol] == 0) v = -1e9f;
                }
                d[c] = v;
            }
        }
    }

    // ---- softmax over full 256-wide rows ----
    float rmax[4];
    #pragma unroll
    for (int mi = 0; mi < 2; mi++) {
        float m0 = -1e30f, m1 = -1e30f;
        #pragma unroll
        for (int nj = 0; nj < 8; nj++) {
            float* d = acc[mi*8+nj];
            m0 = fmaxf(m0, fmaxf(d[0], d[1]));
            m1 = fmaxf(m1, fmaxf(d[2], d[3]));
        }
        rmax[mi*2+0] = m0; rmax[mi*2+1] = m1;
    }
    #pragma unroll
    for (int i = 0; i < 4; i++) {
        rmax[i] = fmaxf(rmax[i], __shfl_xor_sync(0xffffffffu, rmax[i], 1));
        rmax[i] = fmaxf(rmax[i], __shfl_xor_sync(0xffffffffu, rmax[i], 2));
    }
    if (tg == 0) {
        #pragma unroll
        for (int mi = 0; mi < 2; mi++) {
            red[(wr*32 + mi*16 + g    )*4 + wc] = rmax[mi*2+0];
            red[(wr*32 + mi*16 + g + 8)*4 + wc] = rmax[mi*2+1];
        }
    }
    __syncthreads();
    float fmax4[4];
    #pragma unroll
    for (int mi = 0; mi < 2; mi++) {
        int r0 = wr*32 + mi*16 + g, r1 = r0 + 8;
        fmax4[mi*2+0] = fmaxf(fmaxf(red[r0*4+0], red[r0*4+1]), fmaxf(red[r0*4+2], red[r0*4+3]));
        fmax4[mi*2+1] = fmaxf(fmaxf(red[r1*4+0], red[r1*4+1]), fmaxf(red[r1*4+2], red[r1*4+3]));
    }
    __syncthreads();

    float rsum[4] = {0.f, 0.f, 0.f, 0.f};
    #pragma unroll
    for (int mi = 0; mi < 2; mi++) {
        #pragma unroll
        for (int nj = 0; nj < 8; nj++) {
            float* d = acc[mi*8+nj];
            d[0] = __expf(d[0] - fmax4[mi*2+0]);
            d[1] = __expf(d[1] - fmax4[mi*2+0]);
            d[2] = __expf(d[2] - fmax4[mi*2+1]);
            d[3] = __expf(d[3] - fmax4[mi*2+1]);
            rsum[mi*2+0] += d[0] + d[1];
            rsum[mi*2+1] += d[2] + d[3];
        }
    }
    #pragma unroll
    for (int i = 0; i < 4; i++) {
        rsum[i] += __shfl_xor_sync(0xffffffffu, rsum[i], 1);
        rsum[i] += __shfl_xor_sync(0xffffffffu, rsum[i], 2);
    }
    if (tg == 0) {
        #pragma unroll
        for (int mi = 0; mi < 2; mi++) {
            red[(wr*32 + mi*16 + g    )*4 + wc] = rsum[mi*2+0];
            red[(wr*32 + mi*16 + g + 8)*4 + wc] = rsum[mi*2+1];
        }
    }
    __syncthreads();
    float rinv[4];
    #pragma unroll
    for (int mi = 0; mi < 2; mi++) {
        int r0 = wr*32 + mi*16 + g, r1 = r0 + 8;
        rinv[mi*2+0] = 1.f / (red[r0*4+0] + red[r0*4+1] + red[r0*4+2] + red[r0*4+3]);
        rinv[mi*2+1] = 1.f / (red[r1*4+0] + red[r1*4+1] + red[r1*4+2] + red[r1*4+3]);
    }

    // ---- write P to gmem (+ Ps smem for ctx) ----
    float* Pb = P + (long)z * 65536L + (long)rowBase * 256;
    #pragma unroll
    for (int mi = 0; mi < 2; mi++) {
        #pragma unroll
        for (int nj = 0; nj < 8; nj++) {
            float* d = acc[mi*8+nj];
            int col = wc*64 + nj*8 + tg*2;
            int r0 = wr*32 + mi*16 + g;
            float p0 = d[0]*rinv[mi*2+0], p1 = d[1]*rinv[mi*2+0];
            float p2 = d[2]*rinv[mi*2+1], p3 = d[3]*rinv[mi*2+1];
            *reinterpret_cast<float2*>(Pb + (long)r0*256 + col) = make_float2(p0, p1);
            *reinterpret_cast<float2*>(Pb + (long)(r0+8)*256 + col) = make_float2(p2, p3);
            if (CTX) {
                Ps[r0*260 + col] = f2tf(p0); Ps[r0*260 + col + 1] = f2tf(p1);
                Ps[(r0+8)*260 + col] = f2tf(p2); Ps[(r0+8)*260 + col + 1] = f2tf(p3);
            }
        }
    }

    if (CTX) {
        __syncthreads();
        float acc2[4][4];
        #pragma unroll
        for (int i = 0; i < 4; i++) { acc2[i][0]=0.f; acc2[i][1]=0.f; acc2[i][2]=0.f; acc2[i][3]=0.f; }
        #pragma unroll 8
        for (int ks = 0; ks < 32; ks++) {
            const int kk = ks * 8;
            unsigned a[2][4], b[2][2];
            #pragma unroll
            for (int mi = 0; mi < 2; mi++) {
                int mb = wr*32 + mi*16;
                a[mi][0] = Ps[(mb+g  )*260 + kk + tg];
                a[mi][1] = Ps[(mb+g+8)*260 + kk + tg];
                a[mi][2] = Ps[(mb+g  )*260 + kk + tg + 4];
                a[mi][3] = Ps[(mb+g+8)*260 + kk + tg + 4];
            }
            #pragma unroll
            for (int nj = 0; nj < 2; nj++) {
                int nb = wc*16 + nj*8;
                b[nj][0] = Vs[(kk+tg  )*68 + nb + g];
                b[nj][1] = Vs[(kk+tg+4)*68 + nb + g];
            }
            #pragma unroll
            for (int mi = 0; mi < 2; mi++)
                #pragma unroll
                for (int nj = 0; nj < 2; nj++)
                    mma_tf32(acc2[mi*2+nj], a[mi][0],a[mi][1],a[mi][2],a[mi][3],
                             b[nj][0], b[nj][1]);
        }
        float* Cb = Cctx + (long)bb*TT*DD + hh*64;
        #pragma unroll
        for (int mi = 0; mi < 2; mi++) {
            #pragma unroll
            for (int nj = 0; nj < 2; nj++) {
                float* d = acc2[mi*2+nj];
                int r0 = rowBase + wr*32 + mi*16 + g;
                int col = wc*16 + nj*8 + tg*2;
                *reinterpret_cast<float2*>(Cb + (long)r0*DD + col) = make_float2(d[0], d[1]);
                *reinterpret_cast<float2*>(Cb + (long)(r0+8)*DD + col) = make_float2(d[2], d[3]);
            }
        }
    }
}

// ---------------------------------------------------------------------
// bgemm_tf32 (preamble: conv1d K=300, mm_ctx) — unchanged.
// ---------------------------------------------------------------------
template<bool ROWBIAS>
__global__ __launch_bounds__(256) void bgemm_tf32(
    const float* __restrict__ A, const float* __restrict__ B,
    float* __restrict__ C, int M, int N, int K,
    int lda, int ldb, int ldc,
    long strA, long offHA, long strB, long offHB, long strC, long offHC,
    int Hh, const float* __restrict__ bias)
{
    __shared__ unsigned As[128*36];
    __shared__ unsigned Bs[32*72];
    const int tid = threadIdx.x, warp = tid >> 5, lane = tid & 31;
    const int g = lane >> 2, tg = lane & 3;
    const int wr = warp >> 1, wc = warp & 1;
    const int z = blockIdx.z;
    const int bb = z / Hh, hh = z - bb*Hh;

    const float* Ab = A + (long)bb*strA + (long)hh*offHA + (long)blockIdx.y*128*lda;
    const float* Bb = B + (long)bb*strB + (long)hh*offHB + (long)blockIdx.x*64;

    float acc[8][4];
    #pragma unroll
    for (int i = 0; i < 8; i++) { acc[i][0]=0.f; acc[i][1]=0.f; acc[i][2]=0.f; acc[i][3]=0.f; }

    for (int k0 = 0; k0 < K; k0 += 32) {
        if (k0 + 32 <= K && (lda & 3) == 0) {
            #pragma unroll
            for (int p = 0; p < 4; p++) {
                int idx = tid + p*256;
                int r = idx >> 3, c4 = idx & 7;
                float4 v = *reinterpret_cast<const float4*>(Ab + (long)r*lda + k0 + c4*4);
                unsigned* d = &As[r*36 + c4*4];
                d[0]=f2tf(v.x); d[1]=f2tf(v.y); d[2]=f2tf(v.z); d[3]=f2tf(v.w);
            }
        } else {
            #pragma unroll
            for (int p = 0; p < 16; p++) {
                int idx = tid + p*256;
                int r = idx >> 5, c = idx & 31;
                float v = (k0 + c < K) ? Ab[(long)r*lda + k0 + c] : 0.f;
                As[r*36 + c] = f2tf(v);
            }
        }
        #pragma unroll
        for (int p = 0; p < 2; p++) {
            int idx = tid + p*256;
            int r = idx >> 4, c4 = idx & 15;
            float4 v;
            if (k0 + r < K)
                v = *reinterpret_cast<const float4*>(Bb + (long)(k0 + r)*ldb + c4*4);
            else
                v = make_float4(0.f, 0.f, 0.f, 0.f);
            unsigned* d = &Bs[r*72 + c4*4];
            d[0]=f2tf(v.x); d[1]=f2tf(v.y); d[2]=f2tf(v.z); d[3]=f2tf(v.w);
        }
        __syncthreads();
        #pragma unroll
        for (int ks = 0; ks < 4; ks++) {
            const int kk = ks * 8;
            unsigned a[2][4], b[4][2];
            #pragma unroll
            for (int mi = 0; mi < 2; mi++) {
                int mb = wr*32 + mi*16;
                a[mi][0] = As[(mb+g  )*36 + kk + tg];
                a[mi][1] = As[(mb+g+8)*36 + kk + tg];
                a[mi][2] = As[(mb+g  )*36 + kk + tg + 4];
                a[mi][3] = As[(mb+g+8)*36 + kk + tg + 4];
            }
            #pragma unroll
            for (int nj = 0; nj < 4; nj++) {
                int nb = wc*32 + nj*8;
                b[nj][0] = Bs[(kk+tg  )*72 + nb + g];
                b[nj][1] = Bs[(kk+tg+4)*72 + nb + g];
            }
            #pragma unroll
            for (int mi = 0; mi < 2; mi++)
                #pragma unroll
                for (int nj = 0; nj < 4; nj++)
                    mma_tf32(acc[mi*4+nj], a[mi][0],a[mi][1],a[mi][2],a[mi][3],
                             b[nj][0], b[nj][1]);
        }
        __syncthreads();
    }

    float* Cb = C + (long)bb*strC + (long)hh*offHC;
    #pragma unroll
    for (int mi = 0; mi < 2; mi++) {
        #pragma unroll
        for (int nj = 0; nj < 4; nj++) {
            float* d = acc[mi*4+nj];
            int r0 = blockIdx.y*128 + wr*32 + mi*16 + g;
            int col = blockIdx.x*64 + wc*32 + nj*8 + tg*2;
            float b0 = ROWBIAS ? bias[r0] : 0.f;
            float b1 = ROWBIAS ? bias[r0+8] : 0.f;
            *reinterpret_cast<float2*>(Cb + (long)r0*ldc + col) =
                make_float2(d[0]+b0, d[1]+b0);
            *reinterpret_cast<float2*>(Cb + (long)(r0+8)*ldc + col) =
                make_float2(d[2]+b1, d[3]+b1);
        }
    }
}

// ---------------------------------------------------------------------
__global__ __launch_bounds__(256) void add_ln(
    const float* __restrict__ a, const float* __restrict__ b,
    float* __restrict__ out, const float* __restrict__ g,
    const float* __restrict__ beta)
{
    long off = (long)blockIdx.x * DD;
    int t = threadIdx.x;
    float v0 = a[off + t] + b[off + t];
    float v1 = a[off + t + 256] + b[off + t + 256];
    __shared__ float red[256];
    red[t] = v0 + v1; __syncthreads();
    for (int s = 128; s > 0; s >>= 1) { if (t < s) red[t] += red[t+s]; __syncthreads(); }
    float mu = red[0] * (1.f/DD); __syncthreads();
    float d0 = v0 - mu, d1 = v1 - mu;
    red[t] = d0*d0 + d1*d1; __syncthreads();
    for (int s = 128; s > 0; s >>= 1) { if (t < s) red[t] += red[t+s]; __syncthreads(); }
    float rstd = rsqrtf(red[0] * (1.f/DD) + 1e-5f);
    float g0 = g ? g[t] : 1.f,       g1 = g ? g[t+256] : 1.f;
    float b0 = beta ? beta[t] : 0.f, b1 = beta ? beta[t+256] : 0.f;
    out[off + t]       = d0 * rstd * g0 + b0;
    out[off + t + 256] = d1 * rstd * g1 + b1;
}

__global__ void embed_pe(const int* __restrict__ dec,
                         const float* __restrict__ emb,
                         float* __restrict__ x)
{
    long idx = (long)blockIdx.x * blockDim.x + threadIdx.x;
    if (idx >= (long)BT*DD) return;
    int d  = (int)(idx % DD);
    long bt = idx / DD;
    int t  = (int)(bt % TT);
    int tokidx = dec[bt];
    int d2 = d & ~1;
    float div = expf(-logf(10000.f) * (float)d2 / (float)DD);
    float ang = (float)t * div;
    float pe = (d & 1) ? cosf(ang) : sinf(ang);
    x[idx] = emb[(long)tokidx*DD + d] + pe;
}

__global__ void add3(const float* __restrict__ a, const float* __restrict__ bias,
                     const float* __restrict__ c, float* __restrict__ out, long n)
{
    long i = (long)blockIdx.x * blockDim.x + threadIdx.x;
    if (i >= n) return;
    out[i] = a[i] + bias[i % DD] + c[i];
}

__global__ void copyk(const float* __restrict__ src, float* __restrict__ dst, long n)
{
    long i = (long)blockIdx.x * blockDim.x + threadIdx.x;
    if (i < n) dst[i] = src[i];
}

// ---------------------------------------------------------------------
extern "C" void kernel_launch(void* const* d_in, const int* in_sizes, int n_in,
                              void* d_out, int out_size)
{
    const int*   dec     = (const int*)  d_in[0];
    const int*   enc     = (const int*)  d_in[1];
    const float* enc_out = (const float*)d_in[2];
    const float* ast_out = (const float*)d_in[3];
    const float* src_emb = (const float*)d_in[4];
    const float* ast_emb = (const float*)d_in[5];
    const float* emb     = (const float*)d_in[7];
    const float* attn_W  = (const float*)d_in[8];
    const float* ln_g    = (const float*)d_in[9];
    const float* ln_b    = (const float*)d_in[10];
    const float* W1      = (const float*)d_in[11];
    const float* W2      = (const float*)d_in[12];
    const float* conv_w  = (const float*)d_in[13];
    const float* conv_b  = (const float*)d_in[14];
    const float* mffnW   = (const float*)d_in[15];
    const float* mffnb   = (const float*)d_in[16];
    float* out = (float*)d_out;

    float *x,*t,*qkv,*c,*h,*multi,*ast1,*aste,*mm,*mmctx;
    cudaGetSymbolAddress((void**)&x,     g_x);
    cudaGetSymbolAddress((void**)&t,     g_t);
    cudaGetSymbolAddress((void**)&qkv,   g_qkv);
    cudaGetSymbolAddress((void**)&c,     g_c);
    cudaGetSymbolAddress((void**)&h,     g_h);
    cudaGetSymbolAddress((void**)&multi, g_multi);
    cudaGetSymbolAddress((void**)&ast1,  g_ast1);
    cudaGetSymbolAddress((void**)&aste,  g_aste);
    cudaGetSymbolAddress((void**)&mm,    g_mm);
    cudaGetSymbolAddress((void**)&mmctx, g_mmctx);

    const int GM_SMEM  = 2*BUFW*4;                             // 27648
    const int AT_SMEM  = (64*68 + 2*256*68)*4;                 // 156672 (CTX)
    const int MM_SMEM  = (64*68 + 256*68)*4;                   // 87040  (no CTX)
    cudaFuncSetAttribute(gemm2<false,false>, cudaFuncAttributeMaxDynamicSharedMemorySize, GM_SMEM);
    cudaFuncSetAttribute(gemm2<false,true >, cudaFuncAttributeMaxDynamicSharedMemorySize, GM_SMEM);
    cudaFuncSetAttribute(gemm2<true ,false>, cudaFuncAttributeMaxDynamicSharedMemorySize, GM_SMEM);
    cudaFuncSetAttribute(attn_fused<0,false>, cudaFuncAttributeMaxDynamicSharedMemorySize, MM_SMEM);
    cudaFuncSetAttribute(attn_fused<0,true >, cudaFuncAttributeMaxDynamicSharedMemorySize, AT_SMEM);
    cudaFuncSetAttribute(attn_fused<1,true >, cudaFuncAttributeMaxDynamicSharedMemorySize, AT_SMEM);
    cudaFuncSetAttribute(attn_fused<2,true >, cudaFuncAttributeMaxDynamicSharedMemorySize, AT_SMEM);

    float* q = qkv;
    float* k = qkv + (long)BT*DD;
    float* v = qkv + 2L*BT*DD;

    // ---------------- multi_model preamble ----------------
    {
        dim3 grid(DD/64, SS/128, BB);
        bgemm_tf32<true><<<grid, 256>>>(conv_w, ast_out, ast1,
            SS, DD, NA, NA, DD, DD,
            0L, 0L, (long)NA*DD, 0L, (long)SS*DD, 0L, 1, conv_b);
        bgemm_tf32<true><<<grid, 256>>>(conv_w, ast_emb, aste,
            SS, DD, NA, NA, DD, DD,
            0L, 0L, (long)NA*DD, 0L, (long)SS*DD, 0L, 1, conv_b);
    }
    {
        dim3 gs(SS/64, BB);
        attn_fused<0,false><<<gs, 256, MM_SMEM>>>(ast1, enc_out, nullptr, mm, nullptr,
            DD, DD, DD, (long)SS*DD, 0L, (long)SS*DD, 0L,
            1, 0.125f, nullptr, 0);
        dim3 grid2(DD/64, SS/128, BB);
        bgemm_tf32<false><<<grid2, 256>>>(mm, enc_out, mmctx,
            SS, DD, SS, SS, DD, DD,
            (long)SS*SS, 0L, (long)SS*DD, 0L, (long)SS*DD, 0L, 1, nullptr);
    }
    {
        dim3 grid(DD/128, BT/64, 1);
        gemm2<false,false><<<grid, 256, GM_SMEM>>>(src_emb, src_emb, src_emb,
            mffnW, 0L, t, 0L, BT, DD, DD);
        gemm2<false,true ><<<grid, 256, GM_SMEM>>>(aste, aste, aste,
            mffnW + DD*DD, 0L, t, 0L, BT, DD, DD);
        long n = (long)BB*SS*DD;
        add3<<<(int)((n + 255)/256), 256>>>(t, mffnb, mmctx, multi, n);
    }
    embed_pe<<<(BT*DD + 255)/256, 256>>>(dec, emb, x);

    // ---------------- decoder layers ----------------
    dim3 gQKV(DD/128, BT/64, 3);
    dim3 gProj(DD/128, BT/64, 1);
    dim3 gF1(DFF/128, BT/64, 1);
    dim3 gScore(TT/64, BB*HH);

    for (int l = 0; l < LL; l++) {
        for (int a = 0; a < 3; a++) {
            const float* W = attn_W + ((long)(l*3 + a) * 4) * DD * DD;
            const float* Wo = W + 3L*DD*DD;
            const float* xk = (a == 0) ? x : (a == 1 ? enc_out : multi);

            gemm2<false,false><<<gQKV, 256, GM_SMEM>>>(x, xk, xk,
                W, (long)DD*DD, qkv, (long)BT*DD, BT, DD, DD);

            long attnBase = (a == 0 ? SELF_OFF : (a == 1 ? ENC_OFF : AST_OFF))
                            + (long)l * BHTT;
            float* P = out + attnBase;

            if (a == 0)
                attn_fused<1,true><<<gScore, 256, AT_SMEM>>>(q, k, v, P, c,
                    DKK, DD, DD, (long)TT*DD, 64L, (long)TT*DD, 64L,
                    HH, 0.125f, dec, TT);
            else if (a == 1)
                attn_fused<2,true><<<gScore, 256, AT_SMEM>>>(q, k, v, P, c,
                    DKK, DD, DD, (long)TT*DD, 64L, (long)TT*DD, 64L,
                    HH, 0.125f, enc, SS);
            else
                attn_fused<0,true><<<gScore, 256, AT_SMEM>>>(q, k, v, P, c,
                    DKK, DD, DD, (long)TT*DD, 64L, (long)TT*DD, 64L,
                    HH, 0.125f, nullptr, 0);

            gemm2<false,false><<<gProj, 256, GM_SMEM>>>(c, c, c,
                Wo, 0L, t, 0L, BT, DD, DD);
            add_ln<<<BT, 256>>>(t, x, x,
                ln_g + (long)(l*3 + a)*DD, ln_b + (long)(l*3 + a)*DD);
        }
        gemm2<true ,false><<<gF1, 256, GM_SMEM>>>(x, x, x,
            W1 + (long)l*DD*DFF, 0L, h, 0L, BT, DFF, DD);
        gemm2<false,false><<<gProj, 256, GM_SMEM>>>(h, h, h,
            W2 + (long)l*DFF*DD, 0L, t, 0L, BT, DD, DFF);
        add_ln<<<BT, 256>>>(t, x, x, nullptr, nullptr);
    }

    copyk<<<(BT*DD + 255)/256, 256>>>(x, out, (long)BT*DD);
}

// round 6
// speedup vs baseline: 2.0488x; 1.1199x over previous
#include <cuda_runtime.h>
#include <cuda_fp16.h>
#include <math.h>

// Problem dims
#define BB 16
#define TT 256
#define SS 256
#define NA 300
#define DD 512
#define HH 8
#define DKK 64
#define DFF 2048
#define LL 6

#define BT (BB*TT)                 // 4096
#define BHTT ((long)BB*HH*TT*TT)   // 8388608

// d_out layout (floats): x | self_attns | enc_attns | ast_attns
#define SELF_OFF 2097152L
#define ENC_OFF  (SELF_OFF + (long)LL*BHTT)
#define AST_OFF  (ENC_OFF  + (long)LL*BHTT)

// ------------- scratch -------------
__device__ float g_x[BT*DD];
__device__ float g_t[BT*DD];
__device__ float g_qkv[3*BT*DD];
__device__ float g_c[BT*DD];
__device__ float g_h[BT*DFF];
__device__ float g_multi[BB*SS*DD];
__device__ float g_ast1[BB*SS*DD];
__device__ float g_aste[BB*SS*DD];
__device__ float g_mm[BB*SS*SS];
__device__ float g_mmctx[BB*SS*DD];

// ------------- helpers -------------
__device__ __forceinline__ unsigned f2tf(float x) {
    unsigned u; asm("cvt.rna.tf32.f32 %0, %1;" : "=r"(u) : "f"(x)); return u;
}
__device__ __forceinline__ void mma_tf32(float* d,
    unsigned a0, unsigned a1, unsigned a2, unsigned a3,
    unsigned b0, unsigned b1)
{
    asm volatile(
        "mma.sync.aligned.m16n8k8.row.col.f32.tf32.tf32.f32 "
        "{%0,%1,%2,%3},{%4,%5,%6,%7},{%8,%9},{%0,%1,%2,%3};\n"
        : "+f"(d[0]), "+f"(d[1]), "+f"(d[2]), "+f"(d[3])
        : "r"(a0), "r"(a1), "r"(a2), "r"(a3), "r"(b0), "r"(b1));
}
__device__ __forceinline__ unsigned pack_h2(float x, float y) {
    __half2 h = __floats2half2_rn(x, y);
    return *reinterpret_cast<unsigned*>(&h);
}
__device__ __forceinline__ void mma_f16(float* d,
    unsigned a0, unsigned a1, unsigned a2, unsigned a3,
    unsigned b0, unsigned b1)
{
    asm volatile(
        "mma.sync.aligned.m16n8k16.row.col.f32.f16.f16.f32 "
        "{%0,%1,%2,%3},{%4,%5,%6,%7},{%8,%9},{%0,%1,%2,%3};\n"
        : "+f"(d[0]), "+f"(d[1]), "+f"(d[2]), "+f"(d[3])
        : "r"(a0), "r"(a1), "r"(a2), "r"(a3), "r"(b0), "r"(b1));
}

// ---------------------------------------------------------------------
// gemm2 (fp16 MMA, fp32 accum) — unchanged from R5 (proven).
// ---------------------------------------------------------------------
#define VP 20
#define WP 136
#define BUFW (64*VP + 16*WP)   // 3456 words

template<bool RELU, bool ACC>
__global__ __launch_bounds__(256, 2) void gemm2(
    const float* __restrict__ A0, const float* __restrict__ A1,
    const float* __restrict__ A2,
    const float* __restrict__ B0, long strB,
    float* __restrict__ C0, long strC,
    int M, int N, int K)
{
    extern __shared__ unsigned smg[];

    const int tid = threadIdx.x, warp = tid >> 5, lane = tid & 31;
    const int g = lane >> 2, tg = lane & 3;
    const int wr = warp >> 2, wc = warp & 3;
    const int z = blockIdx.z;

    const float* A = (z == 0) ? A0 : (z == 1 ? A1 : A2);
    const float* At = A + (long)blockIdx.y * 64 * K;
    const float* Bt = B0 + (long)z * strB + blockIdx.x * 128;
    float* C = C0 + (long)z * strC;

    const int aR = tid >> 3;
    const int aC = (tid & 7) * 4;
    const int kp = tid >> 5;
    const int bC = (tid & 31) * 4;

    float4 ra[2], rb[4];
    #pragma unroll
    for (int p = 0; p < 2; p++)
        ra[p] = *reinterpret_cast<const float4*>(At + (long)(aR + p*32)*K + aC);
    rb[0] = *reinterpret_cast<const float4*>(Bt + (long)(2*kp     )*N + bC);
    rb[1] = *reinterpret_cast<const float4*>(Bt + (long)(2*kp + 1 )*N + bC);
    rb[2] = *reinterpret_cast<const float4*>(Bt + (long)(2*kp + 16)*N + bC);
    rb[3] = *reinterpret_cast<const float4*>(Bt + (long)(2*kp + 17)*N + bC);

    auto sts = [&](int buf) {
        unsigned* V = smg + buf*BUFW;
        unsigned* W = V + 64*VP;
        #pragma unroll
        for (int p = 0; p < 2; p++) {
            int m = aR + p*32;
            uint2 w;
            w.x = pack_h2(ra[p].x, ra[p].y);
            w.y = pack_h2(ra[p].z, ra[p].w);
            *reinterpret_cast<uint2*>(&V[m*VP + (aC >> 1)]) = w;
        }
        {
            uint4 w0, w1;
            w0.x = pack_h2(rb[0].x, rb[1].x); w0.y = pack_h2(rb[0].y, rb[1].y);
            w0.z = pack_h2(rb[0].z, rb[1].z); w0.w = pack_h2(rb[0].w, rb[1].w);
            *reinterpret_cast<uint4*>(&W[kp*WP + bC]) = w0;
            w1.x = pack_h2(rb[2].x, rb[3].x); w1.y = pack_h2(rb[2].y, rb[3].y);
            w1.z = pack_h2(rb[2].z, rb[3].z); w1.w = pack_h2(rb[2].w, rb[3].w);
            *reinterpret_cast<uint4*>(&W[(kp+8)*WP + bC]) = w1;
        }
    };
    sts(0);
    __syncthreads();

    float acc[8][4];
    #pragma unroll
    for (int i = 0; i < 8; i++) { acc[i][0]=0.f; acc[i][1]=0.f; acc[i][2]=0.f; acc[i][3]=0.f; }

    int cur = 0;
    for (int k0 = 0; k0 < K; k0 += 32) {
        const bool nxt = (k0 + 32) < K;
        if (nxt) {
            #pragma unroll
            for (int p = 0; p < 2; p++)
                ra[p] = *reinterpret_cast<const float4*>(At + (long)(aR + p*32)*K + k0 + 32 + aC);
            rb[0] = *reinterpret_cast<const float4*>(Bt + (long)(k0 + 32 + 2*kp     )*N + bC);
            rb[1] = *reinterpret_cast<const float4*>(Bt + (long)(k0 + 32 + 2*kp + 1 )*N + bC);
            rb[2] = *reinterpret_cast<const float4*>(Bt + (long)(k0 + 32 + 2*kp + 16)*N + bC);
            rb[3] = *reinterpret_cast<const float4*>(Bt + (long)(k0 + 32 + 2*kp + 17)*N + bC);
        }
        const unsigned* V = smg + cur*BUFW;
        const unsigned* W = V + 64*VP;
        #pragma unroll
        for (int kt = 0; kt < 2; kt++) {
            unsigned a[2][4], b[4][2];
            #pragma unroll
            for (int mi = 0; mi < 2; mi++) {
                int r0 = (wr*32 + mi*16 + g)*VP + kt*8 + tg;
                a[mi][0] = V[r0];
                a[mi][1] = V[r0 + 8*VP];
                a[mi][2] = V[r0 + 4];
                a[mi][3] = V[r0 + 8*VP + 4];
            }
            #pragma unroll
            for (int nj = 0; nj < 4; nj++) {
                int nb = wc*32 + nj*8 + g;
                b[nj][0] = W[(kt*8 + tg    )*WP + nb];
                b[nj][1] = W[(kt*8 + tg + 4)*WP + nb];
            }
            #pragma unroll
            for (int mi = 0; mi < 2; mi++)
                #pragma unroll
                for (int nj = 0; nj < 4; nj++)
                    mma_f16(acc[mi*4+nj], a[mi][0],a[mi][1],a[mi][2],a[mi][3],
                            b[nj][0], b[nj][1]);
        }
        if (nxt) {
            sts(cur ^ 1);
            __syncthreads();
            cur ^= 1;
        }
    }

    #pragma unroll
    for (int mi = 0; mi < 2; mi++) {
        #pragma unroll
        for (int nj = 0; nj < 4; nj++) {
            float* d = acc[mi*4+nj];
            int r0 = blockIdx.y*64 + wr*32 + mi*16 + g;
            int col = blockIdx.x*128 + wc*32 + nj*8 + tg*2;
            float2 v0 = make_float2(d[0], d[1]);
            float2 v1 = make_float2(d[2], d[3]);
            float2* p0 = reinterpret_cast<float2*>(C + (long)r0*N + col);
            float2* p1 = reinterpret_cast<float2*>(C + (long)(r0+8)*N + col);
            if (ACC) { float2 o0 = *p0, o1 = *p1; v0.x+=o0.x; v0.y+=o0.y; v1.x+=o1.x; v1.y+=o1.y; }
            if (RELU) { v0.x=fmaxf(v0.x,0.f); v0.y=fmaxf(v0.y,0.f); v1.x=fmaxf(v1.x,0.f); v1.y=fmaxf(v1.y,0.f); }
            *p0 = v0; *p1 = v1;
        }
    }
}

// ---------------------------------------------------------------------
// attn_fused (fp16 MMA): S = scale * Q @ K^T (64 x 256), mask, softmax
// (fp32), write P fp32 to gmem; if CTX also ctx = P @ V via fp16 MMA.
// smem (words): Qs[64*36] | Ks[256*36] | Vs[128*68]; Ps[64*132] aliases.
// Q/K stored half2 [row][k2] (pad 36); V as B-layout half2 [seq2][dk]
// (pad 68); P as half2 [m][k2] (pad 132).
// ---------------------------------------------------------------------
#define QP 36
#define KP 36
#define VBP 68
#define PP 132

template<int MASK, bool CTX>
__global__ __launch_bounds__(256) void attn_fused(
    const float* __restrict__ Q, const float* __restrict__ Km,
    const float* __restrict__ Vm, float* __restrict__ P,
    float* __restrict__ Cctx,
    int Kdim, int lda, int ldb,
    long strA, long offHA, long strB, long offHB,
    int Hh, float scale, const int* __restrict__ tok, int tokStride)
{
    extern __shared__ unsigned sma[];
    unsigned* Qs = sma;                      // 64*36 = 2304
    unsigned* Ks = sma + 64*QP;              // 256*36 = 9216
    unsigned* Vs = sma + 64*QP + 256*KP;     // 128*68 = 8704 (CTX only)
    unsigned* Ps = sma;                      // 64*132 = 8448, aliases Qs/Ks
    __shared__ float red[64*4];

    const int tid = threadIdx.x, warp = tid >> 5, lane = tid & 31;
    const int g = lane >> 2, tg = lane & 3;
    const int wr = warp >> 2, wc = warp & 3;   // wr 0..1 (32 rows), wc 0..3 (64 cols)
    const int z = blockIdx.y;
    const int bb = z / Hh, hh = z - bb*Hh;
    const int rowTile = blockIdx.x;
    const int rowBase = rowTile * 64;

    const float* Qb = Q + (long)bb*strA + (long)hh*offHA + (long)rowBase*lda;
    const float* Kb = Km + (long)bb*strB + (long)hh*offHB;

    float acc[16][4];
    #pragma unroll
    for (int i = 0; i < 16; i++) { acc[i][0]=0.f; acc[i][1]=0.f; acc[i][2]=0.f; acc[i][3]=0.f; }

    for (int k0 = 0; k0 < Kdim; k0 += 64) {
        #pragma unroll
        for (int p = 0; p < 4; p++) {            // Q 64x64 -> half2 [m][k2]
            int idx = tid + p*256;
            int r = idx >> 4, c4 = idx & 15;
            float4 v = *reinterpret_cast<const float4*>(Qb + (long)r*lda + k0 + c4*4);
            uint2 w; w.x = pack_h2(v.x, v.y); w.y = pack_h2(v.z, v.w);
            *reinterpret_cast<uint2*>(&Qs[r*QP + c4*2]) = w;
        }
        #pragma unroll
        for (int p = 0; p < 16; p++) {           // K 256x64 -> half2 [n][k2]
            int idx = tid + p*256;
            int r = idx >> 4, c4 = idx & 15;
            float4 v = *reinterpret_cast<const float4*>(Kb + (long)r*ldb + k0 + c4*4);
            uint2 w; w.x = pack_h2(v.x, v.y); w.y = pack_h2(v.z, v.w);
            *reinterpret_cast<uint2*>(&Ks[r*KP + c4*2]) = w;
        }
        if (CTX && k0 == 0) {                    // V 256x64 -> half2 [seq2][dk]
            const float* Vb = Vm + (long)bb*strB + (long)hh*offHB;
            #pragma unroll
            for (int p = 0; p < 8; p++) {
                int idx = tid + p*256;
                int r2 = idx >> 4, c4 = idx & 15;
                float4 v0 = *reinterpret_cast<const float4*>(Vb + (long)(2*r2  )*ldb + c4*4);
                float4 v1 = *reinterpret_cast<const float4*>(Vb + (long)(2*r2+1)*ldb + c4*4);
                uint4 w;
                w.x = pack_h2(v0.x, v1.x); w.y = pack_h2(v0.y, v1.y);
                w.z = pack_h2(v0.z, v1.z); w.w = pack_h2(v0.w, v1.w);
                *reinterpret_cast<uint4*>(&Vs[r2*VBP + c4*4]) = w;
            }
        }
        __syncthreads();
        #pragma unroll
        for (int kt = 0; kt < 4; kt++) {         // 4 x k16 = 64
            unsigned a[2][4], b[8][2];
            #pragma unroll
            for (int mi = 0; mi < 2; mi++) {
                int mb = wr*32 + mi*16;
                a[mi][0] = Qs[(mb+g  )*QP + kt*8 + tg];
                a[mi][1] = Qs[(mb+g+8)*QP + kt*8 + tg];
                a[mi][2] = Qs[(mb+g  )*QP + kt*8 + tg + 4];
                a[mi][3] = Qs[(mb+g+8)*QP + kt*8 + tg + 4];
            }
            #pragma unroll
            for (int nj = 0; nj < 8; nj++) {
                int nb = wc*64 + nj*8;
                b[nj][0] = Ks[(nb+g)*KP + kt*8 + tg];
                b[nj][1] = Ks[(nb+g)*KP + kt*8 + tg + 4];
            }
            #pragma unroll
            for (int mi = 0; mi < 2; mi++)
                #pragma unroll
                for (int nj = 0; nj < 8; nj++)
                    mma_f16(acc[mi*8+nj], a[mi][0],a[mi][1],a[mi][2],a[mi][3],
                            b[nj][0], b[nj][1]);
        }
        if (k0 + 64 < Kdim) __syncthreads();
    }

    // ---- scale + mask ----
    #pragma unroll
    for (int mi = 0; mi < 2; mi++) {
        #pragma unroll
        for (int nj = 0; nj < 8; nj++) {
            float* d = acc[mi*8+nj];
            int col = wc*64 + nj*8 + tg*2;
            int lr0 = wr*32 + mi*16 + g;
            #pragma unroll
            for (int c = 0; c < 4; c++) {
                int gcol = col + (c & 1);
                int grow = rowBase + lr0 + ((c >> 1) * 8);
                float v = d[c] * scale;
                if (MASK == 1) {
                    if (tok[bb*tokStride + gcol] == 0 || gcol > grow) v = -1e9f;
                } else if (MASK == 2) {
                    if (tok[bb*tokStride + gcol] == 0) v = -1e9f;
                }
                d[c] = v;
            }
        }
    }

    // ---- softmax over full 256-wide rows (fp32) ----
    float rmax[4];
    #pragma unroll
    for (int mi = 0; mi < 2; mi++) {
        float m0 = -1e30f, m1 = -1e30f;
        #pragma unroll
        for (int nj = 0; nj < 8; nj++) {
            float* d = acc[mi*8+nj];
            m0 = fmaxf(m0, fmaxf(d[0], d[1]));
            m1 = fmaxf(m1, fmaxf(d[2], d[3]));
        }
        rmax[mi*2+0] = m0; rmax[mi*2+1] = m1;
    }
    #pragma unroll
    for (int i = 0; i < 4; i++) {
        rmax[i] = fmaxf(rmax[i], __shfl_xor_sync(0xffffffffu, rmax[i], 1));
        rmax[i] = fmaxf(rmax[i], __shfl_xor_sync(0xffffffffu, rmax[i], 2));
    }
    if (tg == 0) {
        #pragma unroll
        for (int mi = 0; mi < 2; mi++) {
            red[(wr*32 + mi*16 + g    )*4 + wc] = rmax[mi*2+0];
            red[(wr*32 + mi*16 + g + 8)*4 + wc] = rmax[mi*2+1];
        }
    }
    __syncthreads();
    float fmax4[4];
    #pragma unroll
    for (int mi = 0; mi < 2; mi++) {
        int r0 = wr*32 + mi*16 + g, r1 = r0 + 8;
        fmax4[mi*2+0] = fmaxf(fmaxf(red[r0*4+0], red[r0*4+1]), fmaxf(red[r0*4+2], red[r0*4+3]));
        fmax4[mi*2+1] = fmaxf(fmaxf(red[r1*4+0], red[r1*4+1]), fmaxf(red[r1*4+2], red[r1*4+3]));
    }
    __syncthreads();

    float rsum[4] = {0.f, 0.f, 0.f, 0.f};
    #pragma unroll
    for (int mi = 0; mi < 2; mi++) {
        #pragma unroll
        for (int nj = 0; nj < 8; nj++) {
            float* d = acc[mi*8+nj];
            d[0] = __expf(d[0] - fmax4[mi*2+0]);
            d[1] = __expf(d[1] - fmax4[mi*2+0]);
            d[2] = __expf(d[2] - fmax4[mi*2+1]);
            d[3] = __expf(d[3] - fmax4[mi*2+1]);
            rsum[mi*2+0] += d[0] + d[1];
            rsum[mi*2+1] += d[2] + d[3];
        }
    }
    #pragma unroll
    for (int i = 0; i < 4; i++) {
        rsum[i] += __shfl_xor_sync(0xffffffffu, rsum[i], 1);
        rsum[i] += __shfl_xor_sync(0xffffffffu, rsum[i], 2);
    }
    if (tg == 0) {
        #pragma unroll
        for (int mi = 0; mi < 2; mi++) {
            red[(wr*32 + mi*16 + g    )*4 + wc] = rsum[mi*2+0];
            red[(wr*32 + mi*16 + g + 8)*4 + wc] = rsum[mi*2+1];
        }
    }
    __syncthreads();
    float rinv[4];
    #pragma unroll
    for (int mi = 0; mi < 2; mi++) {
        int r0 = wr*32 + mi*16 + g, r1 = r0 + 8;
        rinv[mi*2+0] = 1.f / (red[r0*4+0] + red[r0*4+1] + red[r0*4+2] + red[r0*4+3]);
        rinv[mi*2+1] = 1.f / (red[r1*4+0] + red[r1*4+1] + red[r1*4+2] + red[r1*4+3]);
    }

    // ---- write P fp32 to gmem (+ Ps half2 smem for ctx) ----
    float* Pb = P + (long)z * 65536L + (long)rowBase * 256;
    #pragma unroll
    for (int mi = 0; mi < 2; mi++) {
        #pragma unroll
        for (int nj = 0; nj < 8; nj++) {
            float* d = acc[mi*8+nj];
            int col = wc*64 + nj*8 + tg*2;
            int r0 = wr*32 + mi*16 + g;
            float p0 = d[0]*rinv[mi*2+0], p1 = d[1]*rinv[mi*2+0];
            float p2 = d[2]*rinv[mi*2+1], p3 = d[3]*rinv[mi*2+1];
            *reinterpret_cast<float2*>(Pb + (long)r0*256 + col) = make_float2(p0, p1);
            *reinterpret_cast<float2*>(Pb + (long)(r0+8)*256 + col) = make_float2(p2, p3);
            if (CTX) {
                int k2 = wc*32 + nj*4 + tg;
                Ps[r0*PP + k2]     = pack_h2(p0, p1);
                Ps[(r0+8)*PP + k2] = pack_h2(p2, p3);
            }
        }
    }

    if (CTX) {
        __syncthreads();
        // ctx(64x64) = P(64x256) @ V(256x64); fp16 MMA, 16 x k16 steps
        float acc2[4][4];
        #pragma unroll
        for (int i = 0; i < 4; i++) { acc2[i][0]=0.f; acc2[i][1]=0.f; acc2[i][2]=0.f; acc2[i][3]=0.f; }
        #pragma unroll
        for (int kt = 0; kt < 16; kt++) {
            unsigned a[2][4], b[2][2];
            #pragma unroll
            for (int mi = 0; mi < 2; mi++) {
                int mb = wr*32 + mi*16;
                a[mi][0] = Ps[(mb+g  )*PP + kt*8 + tg];
                a[mi][1] = Ps[(mb+g+8)*PP + kt*8 + tg];
                a[mi][2] = Ps[(mb+g  )*PP + kt*8 + tg + 4];
                a[mi][3] = Ps[(mb+g+8)*PP + kt*8 + tg + 4];
            }
            #pragma unroll
            for (int nj = 0; nj < 2; nj++) {
                int nb = wc*16 + nj*8 + g;
                b[nj][0] = Vs[(kt*8 + tg    )*VBP + nb];
                b[nj][1] = Vs[(kt*8 + tg + 4)*VBP + nb];
            }
            #pragma unroll
            for (int mi = 0; mi < 2; mi++)
                #pragma unroll
                for (int nj = 0; nj < 2; nj++)
                    mma_f16(acc2[mi*2+nj], a[mi][0],a[mi][1],a[mi][2],a[mi][3],
                            b[nj][0], b[nj][1]);
        }
        float* Cb = Cctx + (long)bb*TT*DD + hh*64;
        #pragma unroll
        for (int mi = 0; mi < 2; mi++) {
            #pragma unroll
            for (int nj = 0; nj < 2; nj++) {
                float* d = acc2[mi*2+nj];
                int r0 = rowBase + wr*32 + mi*16 + g;
                int col = wc*16 + nj*8 + tg*2;
                *reinterpret_cast<float2*>(Cb + (long)r0*DD + col) = make_float2(d[0], d[1]);
                *reinterpret_cast<float2*>(Cb + (long)(r0+8)*DD + col) = make_float2(d[2], d[3]);
            }
        }
    }
}

// ---------------------------------------------------------------------
// bgemm_tf32 (preamble: conv1d K=300, mm_ctx) — unchanged.
// ---------------------------------------------------------------------
template<bool ROWBIAS>
__global__ __launch_bounds__(256) void bgemm_tf32(
    const float* __restrict__ A, const float* __restrict__ B,
    float* __restrict__ C, int M, int N, int K,
    int lda, int ldb, int ldc,
    long strA, long offHA, long strB, long offHB, long strC, long offHC,
    int Hh, const float* __restrict__ bias)
{
    __shared__ unsigned As[128*36];
    __shared__ unsigned Bs[32*72];
    const int tid = threadIdx.x, warp = tid >> 5, lane = tid & 31;
    const int g = lane >> 2, tg = lane & 3;
    const int wr = warp >> 1, wc = warp & 1;
    const int z = blockIdx.z;
    const int bb = z / Hh, hh = z - bb*Hh;

    const float* Ab = A + (long)bb*strA + (long)hh*offHA + (long)blockIdx.y*128*lda;
    const float* Bb = B + (long)bb*strB + (long)hh*offHB + (long)blockIdx.x*64;

    float acc[8][4];
    #pragma unroll
    for (int i = 0; i < 8; i++) { acc[i][0]=0.f; acc[i][1]=0.f; acc[i][2]=0.f; acc[i][3]=0.f; }

    for (int k0 = 0; k0 < K; k0 += 32) {
        if (k0 + 32 <= K && (lda & 3) == 0) {
            #pragma unroll
            for (int p = 0; p < 4; p++) {
                int idx = tid + p*256;
                int r = idx >> 3, c4 = idx & 7;
                float4 v = *reinterpret_cast<const float4*>(Ab + (long)r*lda + k0 + c4*4);
                unsigned* d = &As[r*36 + c4*4];
                d[0]=f2tf(v.x); d[1]=f2tf(v.y); d[2]=f2tf(v.z); d[3]=f2tf(v.w);
            }
        } else {
            #pragma unroll
            for (int p = 0; p < 16; p++) {
                int idx = tid + p*256;
                int r = idx >> 5, c = idx & 31;
                float v = (k0 + c < K) ? Ab[(long)r*lda + k0 + c] : 0.f;
                As[r*36 + c] = f2tf(v);
            }
        }
        #pragma unroll
        for (int p = 0; p < 2; p++) {
            int idx = tid + p*256;
            int r = idx >> 4, c4 = idx & 15;
            float4 v;
            if (k0 + r < K)
                v = *reinterpret_cast<const float4*>(Bb + (long)(k0 + r)*ldb + c4*4);
            else
                v = make_float4(0.f, 0.f, 0.f, 0.f);
            unsigned* d = &Bs[r*72 + c4*4];
            d[0]=f2tf(v.x); d[1]=f2tf(v.y); d[2]=f2tf(v.z); d[3]=f2tf(v.w);
        }
        __syncthreads();
        #pragma unroll
        for (int ks = 0; ks < 4; ks++) {
            const int kk = ks * 8;
            unsigned a[2][4], b[4][2];
            #pragma unroll
            for (int mi = 0; mi < 2; mi++) {
                int mb = wr*32 + mi*16;
                a[mi][0] = As[(mb+g  )*36 + kk + tg];
                a[mi][1] = As[(mb+g+8)*36 + kk + tg];
                a[mi][2] = As[(mb+g  )*36 + kk + tg + 4];
                a[mi][3] = As[(mb+g+8)*36 + kk + tg + 4];
            }
            #pragma unroll
            for (int nj = 0; nj < 4; nj++) {
                int nb = wc*32 + nj*8;
                b[nj][0] = Bs[(kk+tg  )*72 + nb + g];
                b[nj][1] = Bs[(kk+tg+4)*72 + nb + g];
            }
            #pragma unroll
            for (int mi = 0; mi < 2; mi++)
                #pragma unroll
                for (int nj = 0; nj < 4; nj++)
                    mma_tf32(acc[mi*4+nj], a[mi][0],a[mi][1],a[mi][2],a[mi][3],
                             b[nj][0], b[nj][1]);
        }
        __syncthreads();
    }

    float* Cb = C + (long)bb*strC + (long)hh*offHC;
    #pragma unroll
    for (int mi = 0; mi < 2; mi++) {
        #pragma unroll
        for (int nj = 0; nj < 4; nj++) {
            float* d = acc[mi*4+nj];
            int r0 = blockIdx.y*128 + wr*32 + mi*16 + g;
            int col = blockIdx.x*64 + wc*32 + nj*8 + tg*2;
            float b0 = ROWBIAS ? bias[r0] : 0.f;
            float b1 = ROWBIAS ? bias[r0+8] : 0.f;
            *reinterpret_cast<float2*>(Cb + (long)r0*ldc + col) =
                make_float2(d[0]+b0, d[1]+b0);
            *reinterpret_cast<float2*>(Cb + (long)(r0+8)*ldc + col) =
                make_float2(d[2]+b1, d[3]+b1);
        }
    }
}

// ---------------------------------------------------------------------
// add_ln: warp-shuffle reductions, 2 syncthreads.
__global__ __launch_bounds__(256) void add_ln(
    const float* __restrict__ a, const float* __restrict__ b,
    float* __restrict__ out, const float* __restrict__ g,
    const float* __restrict__ beta)
{
    long off = (long)blockIdx.x * DD;
    int t = threadIdx.x;
    int warp = t >> 5, lane = t & 31;
    float v0 = a[off + t] + b[off + t];
    float v1 = a[off + t + 256] + b[off + t + 256];
    __shared__ float ws[8], ws2[8];

    float s = v0 + v1;
    #pragma unroll
    for (int o = 16; o > 0; o >>= 1) s += __shfl_xor_sync(0xffffffffu, s, o);
    if (lane == 0) ws[warp] = s;
    __syncthreads();
    float mu = (ws[0]+ws[1]+ws[2]+ws[3]+ws[4]+ws[5]+ws[6]+ws[7]) * (1.f/DD);

    float d0 = v0 - mu, d1 = v1 - mu;
    float q = d0*d0 + d1*d1;
    #pragma unroll
    for (int o = 16; o > 0; o >>= 1) q += __shfl_xor_sync(0xffffffffu, q, o);
    if (lane == 0) ws2[warp] = q;
    __syncthreads();
    float rstd = rsqrtf((ws2[0]+ws2[1]+ws2[2]+ws2[3]+ws2[4]+ws2[5]+ws2[6]+ws2[7]) * (1.f/DD) + 1e-5f);

    float g0 = g ? g[t] : 1.f,       g1 = g ? g[t+256] : 1.f;
    float b0 = beta ? beta[t] : 0.f, b1 = beta ? beta[t+256] : 0.f;
    out[off + t]       = d0 * rstd * g0 + b0;
    out[off + t + 256] = d1 * rstd * g1 + b1;
}

__global__ void embed_pe(const int* __restrict__ dec,
                         const float* __restrict__ emb,
                         float* __restrict__ x)
{
    long idx = (long)blockIdx.x * blockDim.x + threadIdx.x;
    if (idx >= (long)BT*DD) return;
    int d  = (int)(idx % DD);
    long bt = idx / DD;
    int t  = (int)(bt % TT);
    int tokidx = dec[bt];
    int d2 = d & ~1;
    float div = expf(-logf(10000.f) * (float)d2 / (float)DD);
    float ang = (float)t * div;
    float pe = (d & 1) ? cosf(ang) : sinf(ang);
    x[idx] = emb[(long)tokidx*DD + d] + pe;
}

__global__ void add3(const float* __restrict__ a, const float* __restrict__ bias,
                     const float* __restrict__ c, float* __restrict__ out, long n)
{
    long i = (long)blockIdx.x * blockDim.x + threadIdx.x;
    if (i >= n) return;
    out[i] = a[i] + bias[i % DD] + c[i];
}

__global__ void copyk(const float* __restrict__ src, float* __restrict__ dst, long n)
{
    long i = (long)blockIdx.x * blockDim.x + threadIdx.x;
    if (i < n) dst[i] = src[i];
}

// ---------------------------------------------------------------------
extern "C" void kernel_launch(void* const* d_in, const int* in_sizes, int n_in,
                              void* d_out, int out_size)
{
    const int*   dec     = (const int*)  d_in[0];
    const int*   enc     = (const int*)  d_in[1];
    const float* enc_out = (const float*)d_in[2];
    const float* ast_out = (const float*)d_in[3];
    const float* src_emb = (const float*)d_in[4];
    const float* ast_emb = (const float*)d_in[5];
    const float* emb     = (const float*)d_in[7];
    const float* attn_W  = (const float*)d_in[8];
    const float* ln_g    = (const float*)d_in[9];
    const float* ln_b    = (const float*)d_in[10];
    const float* W1      = (const float*)d_in[11];
    const float* W2      = (const float*)d_in[12];
    const float* conv_w  = (const float*)d_in[13];
    const float* conv_b  = (const float*)d_in[14];
    const float* mffnW   = (const float*)d_in[15];
    const float* mffnb   = (const float*)d_in[16];
    float* out = (float*)d_out;

    float *x,*t,*qkv,*c,*h,*multi,*ast1,*aste,*mm,*mmctx;
    cudaGetSymbolAddress((void**)&x,     g_x);
    cudaGetSymbolAddress((void**)&t,     g_t);
    cudaGetSymbolAddress((void**)&qkv,   g_qkv);
    cudaGetSymbolAddress((void**)&c,     g_c);
    cudaGetSymbolAddress((void**)&h,     g_h);
    cudaGetSymbolAddress((void**)&multi, g_multi);
    cudaGetSymbolAddress((void**)&ast1,  g_ast1);
    cudaGetSymbolAddress((void**)&aste,  g_aste);
    cudaGetSymbolAddress((void**)&mm,    g_mm);
    cudaGetSymbolAddress((void**)&mmctx, g_mmctx);

    const int GM_SMEM  = 2*BUFW*4;                              // 27648
    const int AT_SMEM  = (64*QP + 256*KP + 128*VBP)*4;          // 80896 (CTX)
    const int MM_SMEM  = (64*QP + 256*KP)*4;                    // 46080 (no CTX)
    cudaFuncSetAttribute(gemm2<false,false>, cudaFuncAttributeMaxDynamicSharedMemorySize, GM_SMEM);
    cudaFuncSetAttribute(gemm2<false,true >, cudaFuncAttributeMaxDynamicSharedMemorySize, GM_SMEM);
    cudaFuncSetAttribute(gemm2<true ,false>, cudaFuncAttributeMaxDynamicSharedMemorySize, GM_SMEM);
    cudaFuncSetAttribute(attn_fused<0,false>, cudaFuncAttributeMaxDynamicSharedMemorySize, MM_SMEM);
    cudaFuncSetAttribute(attn_fused<0,true >, cudaFuncAttributeMaxDynamicSharedMemorySize, AT_SMEM);
    cudaFuncSetAttribute(attn_fused<1,true >, cudaFuncAttributeMaxDynamicSharedMemorySize, AT_SMEM);
    cudaFuncSetAttribute(attn_fused<2,true >, cudaFuncAttributeMaxDynamicSharedMemorySize, AT_SMEM);

    float* q = qkv;
    float* k = qkv + (long)BT*DD;
    float* v = qkv + 2L*BT*DD;

    // ---------------- multi_model preamble ----------------
    {
        dim3 grid(DD/64, SS/128, BB);
        bgemm_tf32<true><<<grid, 256>>>(conv_w, ast_out, ast1,
            SS, DD, NA, NA, DD, DD,
            0L, 0L, (long)NA*DD, 0L, (long)SS*DD, 0L, 1, conv_b);
        bgemm_tf32<true><<<grid, 256>>>(conv_w, ast_emb, aste,
            SS, DD, NA, NA, DD, DD,
            0L, 0L, (long)NA*DD, 0L, (long)SS*DD, 0L, 1, conv_b);
    }
    {
        dim3 gs(SS/64, BB);
        attn_fused<0,false><<<gs, 256, MM_SMEM>>>(ast1, enc_out, nullptr, mm, nullptr,
            DD, DD, DD, (long)SS*DD, 0L, (long)SS*DD, 0L,
            1, 0.125f, nullptr, 0);
        dim3 grid2(DD/64, SS/128, BB);
        bgemm_tf32<false><<<grid2, 256>>>(mm, enc_out, mmctx,
            SS, DD, SS, SS, DD, DD,
            (long)SS*SS, 0L, (long)SS*DD, 0L, (long)SS*DD, 0L, 1, nullptr);
    }
    {
        dim3 grid(DD/128, BT/64, 1);
        gemm2<false,false><<<grid, 256, GM_SMEM>>>(src_emb, src_emb, src_emb,
            mffnW, 0L, t, 0L, BT, DD, DD);
        gemm2<false,true ><<<grid, 256, GM_SMEM>>>(aste, aste, aste,
            mffnW + DD*DD, 0L, t, 0L, BT, DD, DD);
        long n = (long)BB*SS*DD;
        add3<<<(int)((n + 255)/256), 256>>>(t, mffnb, mmctx, multi, n);
    }
    embed_pe<<<(BT*DD + 255)/256, 256>>>(dec, emb, x);

    // ---------------- decoder layers ----------------
    dim3 gQKV(DD/128, BT/64, 3);
    dim3 gProj(DD/128, BT/64, 1);
    dim3 gF1(DFF/128, BT/64, 1);
    dim3 gScore(TT/64, BB*HH);

    for (int l = 0; l < LL; l++) {
        for (int a = 0; a < 3; a++) {
            const float* W = attn_W + ((long)(l*3 + a) * 4) * DD * DD;
            const float* Wo = W + 3L*DD*DD;
            const float* xk = (a == 0) ? x : (a == 1 ? enc_out : multi);

            gemm2<false,false><<<gQKV, 256, GM_SMEM>>>(x, xk, xk,
                W, (long)DD*DD, qkv, (long)BT*DD, BT, DD, DD);

            long attnBase = (a == 0 ? SELF_OFF : (a == 1 ? ENC_OFF : AST_OFF))
                            + (long)l * BHTT;
            float* P = out + attnBase;

            if (a == 0)
                attn_fused<1,true><<<gScore, 256, AT_SMEM>>>(q, k, v, P, c,
                    DKK, DD, DD, (long)TT*DD, 64L, (long)TT*DD, 64L,
                    HH, 0.125f, dec, TT);
            else if (a == 1)
                attn_fused<2,true><<<gScore, 256, AT_SMEM>>>(q, k, v, P, c,
                    DKK, DD, DD, (long)TT*DD, 64L, (long)TT*DD, 64L,
                    HH, 0.125f, enc, SS);
            else
                attn_fused<0,true><<<gScore, 256, AT_SMEM>>>(q, k, v, P, c,
                    DKK, DD, DD, (long)TT*DD, 64L, (long)TT*DD, 64L,
                    HH, 0.125f, nullptr, 0);

            gemm2<false,false><<<gProj, 256, GM_SMEM>>>(c, c, c,
                Wo, 0L, t, 0L, BT, DD, DD);
            add_ln<<<BT, 256>>>(t, x, x,
                ln_g + (long)(l*3 + a)*DD, ln_b + (long)(l*3 + a)*DD);
        }
        gemm2<true ,false><<<gF1, 256, GM_SMEM>>>(x, x, x,
            W1 + (long)l*DD*DFF, 0L, h, 0L, BT, DFF, DD);
        gemm2<false,false><<<gProj, 256, GM_SMEM>>>(h, h, h,
            W2 + (long)l*DFF*DD, 0L, t, 0L, BT, DD, DFF);
        add_ln<<<BT, 256>>>(t, x, x, nullptr, nullptr);
    }

    copyk<<<(BT*DD + 255)/256, 256>>>(x, out, (long)BT*DD);
}